// round 5
// baseline (speedup 1.0000x reference)
#include <cuda_runtime.h>
#include <math.h>

#define NN 512
#define CSd 384
#define CZd 128
#define PROJ 1152
#define FEAT 2112

__device__ __align__(16) float g_Wcat[CSd * PROJ];
__device__ __align__(16) float g_bcat[PROJ];
__device__ __align__(16) float g_proj[NN * PROJ];
__device__ __align__(16) float g_qh[12 * NN * 32];
__device__ __align__(16) float g_khT[12 * 32 * NN];
__device__ __align__(16) float g_attnT[12 * NN * NN];   // bias -> attn (in place)
__device__ __align__(16) float g_vpack[NN * 576];
__device__ __align__(16) float g_oval[NN * 576];
__device__ __align__(16) float g_feats[NN * FEAT];
__device__ __align__(16) float g_part[4 * NN * CSd];

// ------------------------------------------------ K0: pack projection weights
__global__ void pack_kernel(const float* Wq, const float* bq, const float* Wk, const float* bk,
                            const float* Wv, const float* bv, const float* Wqp, const float* bqp,
                            const float* Wkp, const float* bkp, const float* Wvp, const float* bvp) {
    int idx = blockIdx.x * blockDim.x + threadIdx.x;
    if (idx < CSd * PROJ) {
        int r = idx / PROJ, gc = idx % PROJ;
        const float* W; int w, lc;
        if      (gc < 192) { W = Wq;  w = 192; lc = gc;       }
        else if (gc < 384) { W = Wk;  w = 192; lc = gc - 192; }
        else if (gc < 576) { W = Wv;  w = 192; lc = gc - 384; }
        else if (gc < 720) { W = Wqp; w = 144; lc = gc - 576; }
        else if (gc < 864) { W = Wkp; w = 144; lc = gc - 720; }
        else               { W = Wvp; w = 288; lc = gc - 864; }
        g_Wcat[idx] = W[r * w + lc];
    }
    if (idx < PROJ) {
        int gc = idx; const float* bp; int lc;
        if      (gc < 192) { bp = bq;  lc = gc;       }
        else if (gc < 384) { bp = bk;  lc = gc - 192; }
        else if (gc < 576) { bp = bv;  lc = gc - 384; }
        else if (gc < 720) { bp = bqp; lc = gc - 576; }
        else if (gc < 864) { bp = bkp; lc = gc - 720; }
        else               { bp = bvp; lc = gc - 864; }
        g_bcat[idx] = bp[lc];
    }
}

#define FMA16(acc, a, b) do { \
    acc[0][0] += a.x*b.x; acc[0][1] += a.x*b.y; acc[0][2] += a.x*b.z; acc[0][3] += a.x*b.w; \
    acc[1][0] += a.y*b.x; acc[1][1] += a.y*b.y; acc[1][2] += a.y*b.z; acc[1][3] += a.y*b.w; \
    acc[2][0] += a.z*b.x; acc[2][1] += a.z*b.y; acc[2][2] += a.z*b.z; acc[2][3] += a.z*b.w; \
    acc[3][0] += a.w*b.x; acc[3][1] += a.w*b.y; acc[3][2] += a.w*b.z; acc[3][3] += a.w*b.w; \
} while (0)

// ------------------------------------------------ K1: s(512x384) @ Wcat(384x1152) + b
__global__ __launch_bounds__(256) void proj_gemm(const float* __restrict__ sIn) {
    __shared__ __align__(16) float As[32][68];
    __shared__ __align__(16) float Bs[32][68];
    int n0 = blockIdx.x * 64, c0 = blockIdx.y * 64;
    int tid = threadIdx.x, tx = tid % 16, ty = tid / 16;
    float acc[4][4] = {};
    for (int kt = 0; kt < 12; kt++) {
        int kb = kt * 32;
        for (int i = tid; i < 2048; i += 256)
            As[i % 32][i / 32] = sIn[(n0 + i / 32) * CSd + kb + (i % 32)];
        for (int i = tid; i < 2048; i += 256)
            Bs[i / 64][i % 64] = g_Wcat[(kb + i / 64) * PROJ + c0 + (i % 64)];
        __syncthreads();
        #pragma unroll
        for (int kk = 0; kk < 32; kk++) {
            float4 a = *(const float4*)&As[kk][ty * 4];
            float4 b = *(const float4*)&Bs[kk][tx * 4];
            FMA16(acc, a, b);
        }
        __syncthreads();
    }
    #pragma unroll
    for (int i = 0; i < 4; i++) {
        int row = n0 + ty * 4 + i;
        #pragma unroll
        for (int j = 0; j < 4; j++) {
            int col = c0 + tx * 4 + j;
            g_proj[(size_t)row * PROJ + col] = acc[i][j] + g_bcat[col];
        }
    }
}

// ------------------------------------------------ K2: rigid transform + qh/khT pack + vpack (smem only)
__global__ void geom_kernel(const float* __restrict__ trans, const float* __restrict__ rot,
                            const float* __restrict__ head_weights) {
    int n = blockIdx.x, t = threadIdx.x;   // 128 threads
    __shared__ float R[9], T[3], hws[12];
    __shared__ float sqg[144], skg[144], qsq[12], ksq[12];
    if (t < 9)  R[t] = rot[n * 9 + t];
    if (t < 3)  T[t] = trans[n * 3 + t];
    if (t < 12) hws[t] = head_weights[t];
    __syncthreads();
    const float* pr = g_proj + (size_t)n * PROJ;
    if (t < 48) {
        float x = pr[576 + t*3], y = pr[576 + t*3 + 1], zz = pr[576 + t*3 + 2];
        sqg[t*3]     = R[0]*x + R[1]*y + R[2]*zz + T[0];
        sqg[t*3 + 1] = R[3]*x + R[4]*y + R[5]*zz + T[1];
        sqg[t*3 + 2] = R[6]*x + R[7]*y + R[8]*zz + T[2];
    } else if (t < 96) {
        int u = t - 48;
        float x = pr[720 + u*3], y = pr[720 + u*3 + 1], zz = pr[720 + u*3 + 2];
        skg[u*3]     = R[0]*x + R[1]*y + R[2]*zz + T[0];
        skg[u*3 + 1] = R[3]*x + R[4]*y + R[5]*zz + T[1];
        skg[u*3 + 2] = R[6]*x + R[7]*y + R[8]*zz + T[2];
    }
    if (t < 96) {   // v_g directly into vpack (c = 16..39)
        int h = t / 8, p = t % 8;
        float x = pr[864 + t*3], y = pr[864 + t*3 + 1], zz = pr[864 + t*3 + 2];
        float* vp = &g_vpack[(size_t)n*576 + h*48 + 16 + p*3];
        vp[0] = R[0]*x + R[1]*y + R[2]*zz + T[0];
        vp[1] = R[3]*x + R[4]*y + R[5]*zz + T[1];
        vp[2] = R[6]*x + R[7]*y + R[8]*zz + T[2];
    }
    __syncthreads();
    if (t < 12) {
        float sq = 0.f, sk = 0.f;
        #pragma unroll
        for (int j = 0; j < 12; j++) {
            float a = sqg[t*12 + j]; sq += a * a;
            float b = skg[t*12 + j]; sk += b * b;
        }
        qsq[t] = sq; ksq[t] = sk;
    }
    __syncthreads();
    for (int i = t; i < 384; i += 128) {
        int h = i / 32, c = i % 32;
        float hw = hws[h];
        float qv = 0.f, kv = 0.f;
        if (c < 16) {
            qv = 0.25f * pr[h*16 + c];
            kv = pr[192 + h*16 + c];
        } else if (c < 28) {
            qv = hw * sqg[h*12 + (c - 16)];
            kv = skg[h*12 + (c - 16)];
        } else if (c == 28) {
            qv = -0.5f * hw * qsq[h];
            kv = 1.f;
        } else if (c == 29) {
            qv = -0.5f * hw;
            kv = ksq[h];
        }
        g_qh[((size_t)h*NN + n)*32 + c] = qv;
        g_khT[((size_t)h*32 + c)*NN + n] = kv;
    }
    for (int i = t; i < 576; i += 128) {
        int h = i / 48, c = i % 48;
        if (c < 16)       g_vpack[(size_t)n*576 + i] = pr[384 + h*16 + c];
        else if (c >= 40) g_vpack[(size_t)n*576 + i] = 0.f;
    }
}

// ------------------------------------------------ K2b: bias -> g_attnT[h][n][m]
__global__ __launch_bounds__(256) void bias_kernel(const float* __restrict__ z,
        const float* __restrict__ trans, const float* __restrict__ Wb, const float* __restrict__ bb,
        const float* __restrict__ dist_emb, const float* __restrict__ scale_logits) {
    int n = blockIdx.x, tid = threadIdx.x;
    __shared__ __align__(16) float4 wT[12][32];
    __shared__ float des[64 * 12], phs[36], bbs[12], Tn[3];
    for (int i = tid; i < 12 * 32; i += 256) {
        int h = i / 32, c4 = i % 32;
        wT[h][c4] = make_float4(Wb[(c4*4)*12 + h], Wb[(c4*4+1)*12 + h],
                                Wb[(c4*4+2)*12 + h], Wb[(c4*4+3)*12 + h]);
    }
    for (int i = tid; i < 768; i += 256) des[i] = dist_emb[i];
    if (tid < 12) {
        bbs[tid] = bb[tid];
        float e0 = expf(scale_logits[tid]), e1 = expf(scale_logits[12 + tid]), e2 = expf(scale_logits[24 + tid]);
        float inv = 1.f / (e0 + e1 + e2);
        phs[tid] = e0 * inv; phs[12 + tid] = e1 * inv; phs[24 + tid] = e2 * inv;
    }
    if (tid < 3) Tn[tid] = trans[n*3 + tid];
    __syncthreads();
    float acc[2][12];
    #pragma unroll
    for (int j = 0; j < 2; j++) {
        int m = tid + j * 256;
        float dx = Tn[0] - trans[m*3], dy = Tn[1] - trans[m*3+1], dz = Tn[2] - trans[m*3+2];
        float d = sqrtf(dx*dx + dy*dy + dz*dz);
        int bin = max(0, min(63, (int)ceilf(d * 2.f) - 1));
        float w0 = (d <= 5.f) ? 1.f : 0.f;
        float w1 = (d > 5.f && d <= 15.f) ? 1.f : 0.f;
        #pragma unroll
        for (int h = 0; h < 12; h++)
            acc[j][h] = bbs[h] + des[bin*12 + h] + w0*phs[h] + w1*phs[12 + h] + phs[24 + h];
    }
    const float4* z4 = (const float4*)z + (size_t)n * NN * 32;
    #pragma unroll 2
    for (int c4 = 0; c4 < 32; c4++) {
        float4 zv0 = z4[(size_t)tid * 32 + c4];
        float4 zv1 = z4[(size_t)(tid + 256) * 32 + c4];
        #pragma unroll
        for (int h = 0; h < 12; h++) {
            float4 w = wT[h][c4];
            acc[0][h] += zv0.x*w.x + zv0.y*w.y + zv0.z*w.z + zv0.w*w.w;
            acc[1][h] += zv1.x*w.x + zv1.y*w.y + zv1.z*w.z + zv1.w*w.w;
        }
    }
    #pragma unroll
    for (int h = 0; h < 12; h++) {
        g_attnT[((size_t)h*NN + n)*NN + tid]       = acc[0][h];
        g_attnT[((size_t)h*NN + n)*NN + tid + 256] = acc[1][h];
    }
}

// ------------------------------------------------ K3: fused logits GEMM + bias + softmax -> attn
__global__ __launch_bounds__(256) void logits_softmax_kernel() {
    __shared__ __align__(16) float Qs[32][68];
    __shared__ __align__(16) float Ks[32][260];
    int n0 = blockIdx.x * 64, h = blockIdx.y;
    int tid = threadIdx.x, tx = tid % 16, ty = tid / 16;
    for (int i = tid; i < 2048; i += 256)
        Qs[i % 32][i / 32] = g_qh[((size_t)h*NN + n0 + i/32)*32 + (i % 32)];
    float acc[8][4][4] = {};
    #pragma unroll
    for (int half = 0; half < 2; half++) {
        __syncthreads();
        for (int i = tid; i < 8192; i += 256)
            Ks[i / 256][i % 256] = g_khT[((size_t)h*32 + i/256)*NN + half*256 + (i % 256)];
        __syncthreads();
        #pragma unroll
        for (int mt = 0; mt < 4; mt++) {
            int mo = mt*64 + tx*4;
            #pragma unroll
            for (int kk = 0; kk < 32; kk++) {
                float4 a = *(const float4*)&Qs[kk][ty * 4];
                float4 b = *(const float4*)&Ks[kk][mo];
                FMA16(acc[half*4 + mt], a, b);
            }
        }
    }
    // add bias (resident in g_attnT)
    #pragma unroll
    for (int mt = 0; mt < 8; mt++)
        #pragma unroll
        for (int i = 0; i < 4; i++) {
            float4 bv = *(const float4*)&g_attnT[((size_t)h*NN + n0 + ty*4 + i)*NN + mt*64 + tx*4];
            acc[mt][i][0] += bv.x; acc[mt][i][1] += bv.y;
            acc[mt][i][2] += bv.z; acc[mt][i][3] += bv.w;
        }
    // softmax over m (32 vals/thread/row, reduce over 16-lane group)
    #pragma unroll
    for (int i = 0; i < 4; i++) {
        float mx = -1e30f;
        #pragma unroll
        for (int mt = 0; mt < 8; mt++)
            #pragma unroll
            for (int j = 0; j < 4; j++) mx = fmaxf(mx, acc[mt][i][j]);
        #pragma unroll
        for (int o = 8; o; o >>= 1) mx = fmaxf(mx, __shfl_xor_sync(0xffffffffu, mx, o));
        float sm = 0.f;
        #pragma unroll
        for (int mt = 0; mt < 8; mt++)
            #pragma unroll
            for (int j = 0; j < 4; j++) {
                float e = __expf(acc[mt][i][j] - mx);
                acc[mt][i][j] = e; sm += e;
            }
        #pragma unroll
        for (int o = 8; o; o >>= 1) sm += __shfl_xor_sync(0xffffffffu, sm, o);
        float inv = 1.f / sm;
        #pragma unroll
        for (int mt = 0; mt < 8; mt++)
            #pragma unroll
            for (int j = 0; j < 4; j++) acc[mt][i][j] *= inv;
    }
    #pragma unroll
    for (int mt = 0; mt < 8; mt++)
        #pragma unroll
        for (int i = 0; i < 4; i++) {
            float4 st = make_float4(acc[mt][i][0], acc[mt][i][1], acc[mt][i][2], acc[mt][i][3]);
            *(float4*)&g_attnT[((size_t)h*NN + n0 + ty*4 + i)*NN + mt*64 + tx*4] = st;
        }
}

// ------------------------------------------------ K4a: per-head attn @ [v|v_g]  (512x48x512)
__global__ __launch_bounds__(256) void outval_gemm() {
    __shared__ __align__(16) float As[32][68];
    __shared__ float Bs[32][48];
    int n0 = blockIdx.x * 64, h = blockIdx.y;
    int tid = threadIdx.x, tx = tid % 16, ty = tid / 16;
    float acc[4][3] = {};
    for (int kt = 0; kt < 16; kt++) {
        int kb = kt * 32;
        for (int i = tid; i < 2048; i += 256)
            As[i % 32][i / 32] = g_attnT[((size_t)h*NN + n0 + i/32)*NN + kb + (i % 32)];
        for (int i = tid; i < 1536; i += 256)
            Bs[i / 48][i % 48] = g_vpack[(size_t)(kb + i/48) * 576 + h*48 + (i % 48)];
        __syncthreads();
        #pragma unroll
        for (int kk = 0; kk < 32; kk++) {
            float4 a = *(const float4*)&As[kk][ty * 4];
            float b0 = Bs[kk][tx*3], b1 = Bs[kk][tx*3+1], b2 = Bs[kk][tx*3+2];
            acc[0][0] += a.x*b0; acc[0][1] += a.x*b1; acc[0][2] += a.x*b2;
            acc[1][0] += a.y*b0; acc[1][1] += a.y*b1; acc[1][2] += a.y*b2;
            acc[2][0] += a.z*b0; acc[2][1] += a.z*b1; acc[2][2] += a.z*b2;
            acc[3][0] += a.w*b0; acc[3][1] += a.w*b1; acc[3][2] += a.w*b2;
        }
        __syncthreads();
    }
    #pragma unroll
    for (int i = 0; i < 4; i++)
        #pragma unroll
        for (int j = 0; j < 3; j++)
            g_oval[(size_t)(n0 + ty*4 + i) * 576 + h*48 + tx*3 + j] = acc[i][j];
}

// ------------------------------------------------ K4b: pair_feat = attn @ z  per n
__global__ __launch_bounds__(256) void pairfeat_kernel(const float* __restrict__ z) {
    __shared__ float sm[12288];
    int n = blockIdx.x, tid = threadIdx.x;
    int c4 = tid & 31, mp = tid >> 5;
    for (int i = tid; i < 6144; i += 256)
        sm[i] = g_attnT[((size_t)(i/512)*NN + n)*NN + (i % 512)];
    __syncthreads();
    float acc[12][4] = {};
    const float4* z4 = (const float4*)z + (size_t)n * NN * 32;
    #pragma unroll 4
    for (int m = mp*64; m < mp*64 + 64; m++) {
        float4 zv = z4[(size_t)m * 32 + c4];
        #pragma unroll
        for (int h = 0; h < 12; h++) {
            float a = sm[h*512 + m];
            acc[h][0] += a*zv.x; acc[h][1] += a*zv.y; acc[h][2] += a*zv.z; acc[h][3] += a*zv.w;
        }
    }
    __syncthreads();
    #pragma unroll
    for (int h = 0; h < 12; h++)
        #pragma unroll
        for (int j = 0; j < 4; j++)
            sm[mp*1536 + h*128 + c4*4 + j] = acc[h][j];
    __syncthreads();
    for (int o = tid; o < 1536; o += 256) {
        float s = 0.f;
        #pragma unroll
        for (int p = 0; p < 8; p++) s += sm[p*1536 + o];
        int h = o >> 7, c = o & 127;
        g_feats[(size_t)n*FEAT + h*176 + 48 + c] = s;
    }
}

// ------------------------------------------------ K5: local frame + norms + scalar copy
__global__ void assemble_kernel(const float* __restrict__ trans, const float* __restrict__ rot) {
    int n = blockIdx.x, t = threadIdx.x;  // 288 threads
    __shared__ float R[9], T[3];
    if (t < 9) R[t] = rot[n*9 + t];
    if (t < 3) T[t] = trans[n*3 + t];
    __syncthreads();
    if (t < 96) {
        int h = t / 8, p = t % 8;
        const float* g = &g_oval[(size_t)n*576 + h*48 + 16 + p*3];
        float gx = g[0] - T[0], gy = g[1] - T[1], gz = g[2] - T[2];
        float lx = R[0]*gx + R[3]*gy + R[6]*gz;
        float ly = R[1]*gx + R[4]*gy + R[7]*gz;
        float lz = R[2]*gx + R[5]*gy + R[8]*gz;
        float* f = &g_feats[(size_t)n*FEAT + h*176];
        f[16 + p*3] = lx; f[16 + p*3 + 1] = ly; f[16 + p*3 + 2] = lz;
        f[40 + p] = sqrtf(lx*lx + ly*ly + lz*lz);
    } else if (t < 96 + 192) {
        int u = t - 96, h = u / 16, c = u % 16;
        g_feats[(size_t)n*FEAT + h*176 + c] = g_oval[(size_t)n*576 + h*48 + c];
    }
}

// ------------------------------------------------ K6: feats(512x2112) @ Wout(2112x384), split-K
__global__ __launch_bounds__(256) void final_gemm(const float* __restrict__ Wout) {
    __shared__ __align__(16) float As[32][68];
    __shared__ __align__(16) float Bs[32][68];
    int n0 = blockIdx.x * 64, c0 = blockIdx.y * 64, sp = blockIdx.z;
    int tid = threadIdx.x, tx = tid % 16, ty = tid / 16;
    int k0 = sp * 17, k1 = min(66, k0 + 17);
    float acc[4][4] = {};
    for (int kt = k0; kt < k1; kt++) {
        int kb = kt * 32;
        for (int i = tid; i < 2048; i += 256)
            As[i % 32][i / 32] = g_feats[(size_t)(n0 + i/32)*FEAT + kb + (i % 32)];
        for (int i = tid; i < 2048; i += 256)
            Bs[i / 64][i % 64] = Wout[(size_t)(kb + i/64)*CSd + c0 + (i % 64)];
        __syncthreads();
        #pragma unroll
        for (int kk = 0; kk < 32; kk++) {
            float4 a = *(const float4*)&As[kk][ty * 4];
            float4 b = *(const float4*)&Bs[kk][tx * 4];
            FMA16(acc, a, b);
        }
        __syncthreads();
    }
    #pragma unroll
    for (int i = 0; i < 4; i++)
        #pragma unroll
        for (int j = 0; j < 4; j++)
            g_part[(size_t)sp*NN*CSd + (n0 + ty*4 + i)*CSd + c0 + tx*4 + j] = acc[i][j];
}

__global__ void finalize_kernel(const float* __restrict__ bout, float* __restrict__ out) {
    int idx = blockIdx.x * blockDim.x + threadIdx.x;
    if (idx < NN * CSd) {
        int c = idx % CSd;
        out[idx] = bout[c] + g_part[idx] + g_part[NN*CSd + idx]
                 + g_part[2*NN*CSd + idx] + g_part[3*NN*CSd + idx];
    }
}

extern "C" void kernel_launch(void* const* d_in, const int* in_sizes, int n_in,
                              void* d_out, int out_size) {
    const float* s       = (const float*)d_in[0];
    const float* z       = (const float*)d_in[1];
    const float* trans   = (const float*)d_in[2];
    const float* rot     = (const float*)d_in[3];
    const float* Wq  = (const float*)d_in[5];  const float* bq  = (const float*)d_in[6];
    const float* Wk  = (const float*)d_in[7];  const float* bk  = (const float*)d_in[8];
    const float* Wv  = (const float*)d_in[9];  const float* bv  = (const float*)d_in[10];
    const float* Wqp = (const float*)d_in[11]; const float* bqp = (const float*)d_in[12];
    const float* Wkp = (const float*)d_in[13]; const float* bkp = (const float*)d_in[14];
    const float* Wvp = (const float*)d_in[15]; const float* bvp = (const float*)d_in[16];
    const float* Wb  = (const float*)d_in[17]; const float* bb  = (const float*)d_in[18];
    const float* dist_emb      = (const float*)d_in[19];
    const float* scale_logits  = (const float*)d_in[20];
    const float* head_weights  = (const float*)d_in[21];
    const float* Wout = (const float*)d_in[22];
    const float* bout = (const float*)d_in[23];
    float* out = (float*)d_out;

    pack_kernel<<<(CSd*PROJ + 255)/256, 256>>>(Wq,bq,Wk,bk,Wv,bv,Wqp,bqp,Wkp,bkp,Wvp,bvp);
    bias_kernel<<<NN, 256>>>(z, trans, Wb, bb, dist_emb, scale_logits);
    proj_gemm<<<dim3(8, 18), 256>>>(s);
    geom_kernel<<<NN, 128>>>(trans, rot, head_weights);
    logits_softmax_kernel<<<dim3(8, 12), 256>>>();
    outval_gemm<<<dim3(8, 12), 256>>>();
    pairfeat_kernel<<<NN, 256>>>(z);
    assemble_kernel<<<NN, 288>>>(trans, rot);
    final_gemm<<<dim3(8, 6, 4), 256>>>(Wout);
    finalize_kernel<<<(NN*CSd + 255)/256, 256>>>(bout, out);
}

// round 7
// speedup vs baseline: 1.4081x; 1.4081x over previous
#include <cuda_runtime.h>
#include <math.h>

#define NN 512
#define CSd 384
#define CZd 128
#define PROJ 1152
#define FEAT 2112

__device__ __align__(16) float g_Wcat[CSd * PROJ];
__device__ __align__(16) float g_bcat[PROJ];
__device__ __align__(16) float g_proj[NN * PROJ];
__device__ __align__(16) float g_qh[12 * NN * 32];
__device__ __align__(16) float g_khT[12 * 32 * NN];
__device__ __align__(16) float g_attnT[12 * NN * NN];   // bias -> attn (in place)
__device__ __align__(16) float g_vpack[NN * 576];
__device__ __align__(16) float g_oval[NN * 576];
__device__ __align__(16) float g_feats[NN * FEAT];
__device__ __align__(16) float g_part[4 * NN * CSd];

// ------------------------------------------------ K0: pack projection weights
__global__ void pack_kernel(const float* Wq, const float* bq, const float* Wk, const float* bk,
                            const float* Wv, const float* bv, const float* Wqp, const float* bqp,
                            const float* Wkp, const float* bkp, const float* Wvp, const float* bvp) {
    int idx = blockIdx.x * blockDim.x + threadIdx.x;
    if (idx < CSd * PROJ) {
        int r = idx / PROJ, gc = idx % PROJ;
        const float* W; int w, lc;
        if      (gc < 192) { W = Wq;  w = 192; lc = gc;       }
        else if (gc < 384) { W = Wk;  w = 192; lc = gc - 192; }
        else if (gc < 576) { W = Wv;  w = 192; lc = gc - 384; }
        else if (gc < 720) { W = Wqp; w = 144; lc = gc - 576; }
        else if (gc < 864) { W = Wkp; w = 144; lc = gc - 720; }
        else               { W = Wvp; w = 288; lc = gc - 864; }
        g_Wcat[idx] = W[r * w + lc];
    }
    if (idx < PROJ) {
        int gc = idx; const float* bp; int lc;
        if      (gc < 192) { bp = bq;  lc = gc;       }
        else if (gc < 384) { bp = bk;  lc = gc - 192; }
        else if (gc < 576) { bp = bv;  lc = gc - 384; }
        else if (gc < 720) { bp = bqp; lc = gc - 576; }
        else if (gc < 864) { bp = bkp; lc = gc - 720; }
        else               { bp = bvp; lc = gc - 864; }
        g_bcat[idx] = bp[lc];
    }
}

#define FMA16(acc, a, b) do { \
    acc[0][0] += a.x*b.x; acc[0][1] += a.x*b.y; acc[0][2] += a.x*b.z; acc[0][3] += a.x*b.w; \
    acc[1][0] += a.y*b.x; acc[1][1] += a.y*b.y; acc[1][2] += a.y*b.z; acc[1][3] += a.y*b.w; \
    acc[2][0] += a.z*b.x; acc[2][1] += a.z*b.y; acc[2][2] += a.z*b.z; acc[2][3] += a.z*b.w; \
    acc[3][0] += a.w*b.x; acc[3][1] += a.w*b.y; acc[3][2] += a.w*b.z; acc[3][3] += a.w*b.w; \
} while (0)

// ------------------------------------------------ K1: s(512x384) @ Wcat(384x1152) + b
__global__ __launch_bounds__(256) void proj_gemm(const float* __restrict__ sIn) {
    __shared__ __align__(16) float As[32][68];
    __shared__ __align__(16) float Bs[32][68];
    int n0 = blockIdx.x * 64, c0 = blockIdx.y * 64;
    int tid = threadIdx.x, tx = tid % 16, ty = tid / 16;
    float acc[4][4] = {};
    for (int kt = 0; kt < 12; kt++) {
        int kb = kt * 32;
        for (int i = tid; i < 2048; i += 256)
            As[i % 32][i / 32] = sIn[(n0 + i / 32) * CSd + kb + (i % 32)];
        for (int i = tid; i < 2048; i += 256)
            Bs[i / 64][i % 64] = g_Wcat[(kb + i / 64) * PROJ + c0 + (i % 64)];
        __syncthreads();
        #pragma unroll
        for (int kk = 0; kk < 32; kk++) {
            float4 a = *(const float4*)&As[kk][ty * 4];
            float4 b = *(const float4*)&Bs[kk][tx * 4];
            FMA16(acc, a, b);
        }
        __syncthreads();
    }
    #pragma unroll
    for (int i = 0; i < 4; i++) {
        int row = n0 + ty * 4 + i;
        #pragma unroll
        for (int j = 0; j < 4; j++) {
            int col = c0 + tx * 4 + j;
            g_proj[(size_t)row * PROJ + col] = acc[i][j] + g_bcat[col];
        }
    }
}

// ------------------------------------------------ K2: rigid transform + qh/khT pack + vpack
__global__ void geom_kernel(const float* __restrict__ trans, const float* __restrict__ rot,
                            const float* __restrict__ head_weights) {
    int n = blockIdx.x, t = threadIdx.x;   // 128 threads
    __shared__ float R[9], T[3], hws[12];
    __shared__ float sqg[144], skg[144], qsq[12], ksq[12];
    if (t < 9)  R[t] = rot[n * 9 + t];
    if (t < 3)  T[t] = trans[n * 3 + t];
    if (t < 12) hws[t] = head_weights[t];
    __syncthreads();
    const float* pr = g_proj + (size_t)n * PROJ;
    if (t < 48) {
        float x = pr[576 + t*3], y = pr[576 + t*3 + 1], zz = pr[576 + t*3 + 2];
        sqg[t*3]     = R[0]*x + R[1]*y + R[2]*zz + T[0];
        sqg[t*3 + 1] = R[3]*x + R[4]*y + R[5]*zz + T[1];
        sqg[t*3 + 2] = R[6]*x + R[7]*y + R[8]*zz + T[2];
    } else if (t < 96) {
        int u = t - 48;
        float x = pr[720 + u*3], y = pr[720 + u*3 + 1], zz = pr[720 + u*3 + 2];
        skg[u*3]     = R[0]*x + R[1]*y + R[2]*zz + T[0];
        skg[u*3 + 1] = R[3]*x + R[4]*y + R[5]*zz + T[1];
        skg[u*3 + 2] = R[6]*x + R[7]*y + R[8]*zz + T[2];
    }
    if (t < 96) {
        int h = t / 8, p = t % 8;
        float x = pr[864 + t*3], y = pr[864 + t*3 + 1], zz = pr[864 + t*3 + 2];
        float* vp = &g_vpack[(size_t)n*576 + h*48 + 16 + p*3];
        vp[0] = R[0]*x + R[1]*y + R[2]*zz + T[0];
        vp[1] = R[3]*x + R[4]*y + R[5]*zz + T[1];
        vp[2] = R[6]*x + R[7]*y + R[8]*zz + T[2];
    }
    __syncthreads();
    if (t < 12) {
        float sq = 0.f, sk = 0.f;
        #pragma unroll
        for (int j = 0; j < 12; j++) {
            float a = sqg[t*12 + j]; sq += a * a;
            float b = skg[t*12 + j]; sk += b * b;
        }
        qsq[t] = sq; ksq[t] = sk;
    }
    __syncthreads();
    for (int i = t; i < 384; i += 128) {
        int h = i / 32, c = i % 32;
        float hw = hws[h];
        float qv = 0.f, kv = 0.f;
        if (c < 16) {
            qv = 0.25f * pr[h*16 + c];
            kv = pr[192 + h*16 + c];
        } else if (c < 28) {
            qv = hw * sqg[h*12 + (c - 16)];
            kv = skg[h*12 + (c - 16)];
        } else if (c == 28) {
            qv = -0.5f * hw * qsq[h];
            kv = 1.f;
        } else if (c == 29) {
            qv = -0.5f * hw;
            kv = ksq[h];
        }
        g_qh[((size_t)h*NN + n)*32 + c] = qv;
        g_khT[((size_t)h*32 + c)*NN + n] = kv;
    }
    for (int i = t; i < 576; i += 128) {
        int h = i / 48, c = i % 48;
        if (c < 16)       g_vpack[(size_t)n*576 + i] = pr[384 + h*16 + c];
        else if (c >= 40) g_vpack[(size_t)n*576 + i] = 0.f;
    }
}

// ------------------------------------------------ K2b: bias -> g_attnT[h][n][m]
__global__ __launch_bounds__(256) void bias_kernel(const float* __restrict__ z,
        const float* __restrict__ trans, const float* __restrict__ Wb, const float* __restrict__ bb,
        const float* __restrict__ dist_emb, const float* __restrict__ scale_logits) {
    int n = blockIdx.x, tid = threadIdx.x;
    __shared__ __align__(16) float4 wT[12][32];
    __shared__ float des[64 * 12], phs[36], bbs[12], Tn[3];
    for (int i = tid; i < 12 * 32; i += 256) {
        int h = i / 32, c4 = i % 32;
        wT[h][c4] = make_float4(Wb[(c4*4)*12 + h], Wb[(c4*4+1)*12 + h],
                                Wb[(c4*4+2)*12 + h], Wb[(c4*4+3)*12 + h]);
    }
    for (int i = tid; i < 768; i += 256) des[i] = dist_emb[i];
    if (tid < 12) {
        bbs[tid] = bb[tid];
        float e0 = expf(scale_logits[tid]), e1 = expf(scale_logits[12 + tid]), e2 = expf(scale_logits[24 + tid]);
        float inv = 1.f / (e0 + e1 + e2);
        phs[tid] = e0 * inv; phs[12 + tid] = e1 * inv; phs[24 + tid] = e2 * inv;
    }
    if (tid < 3) Tn[tid] = trans[n*3 + tid];
    __syncthreads();
    float acc[2][12];
    #pragma unroll
    for (int j = 0; j < 2; j++) {
        int m = tid + j * 256;
        float dx = Tn[0] - trans[m*3], dy = Tn[1] - trans[m*3+1], dz = Tn[2] - trans[m*3+2];
        float d = sqrtf(dx*dx + dy*dy + dz*dz);
        int bin = max(0, min(63, (int)ceilf(d * 2.f) - 1));
        float w0 = (d <= 5.f) ? 1.f : 0.f;
        float w1 = (d > 5.f && d <= 15.f) ? 1.f : 0.f;
        #pragma unroll
        for (int h = 0; h < 12; h++)
            acc[j][h] = bbs[h] + des[bin*12 + h] + w0*phs[h] + w1*phs[12 + h] + phs[24 + h];
    }
    const float4* z4 = (const float4*)z + (size_t)n * NN * 32;
    #pragma unroll 2
    for (int c4 = 0; c4 < 32; c4++) {
        float4 zv0 = z4[(size_t)tid * 32 + c4];
        float4 zv1 = z4[(size_t)(tid + 256) * 32 + c4];
        #pragma unroll
        for (int h = 0; h < 12; h++) {
            float4 w = wT[h][c4];
            acc[0][h] += zv0.x*w.x + zv0.y*w.y + zv0.z*w.z + zv0.w*w.w;
            acc[1][h] += zv1.x*w.x + zv1.y*w.y + zv1.z*w.z + zv1.w*w.w;
        }
    }
    #pragma unroll
    for (int h = 0; h < 12; h++) {
        g_attnT[((size_t)h*NN + n)*NN + tid]       = acc[0][h];
        g_attnT[((size_t)h*NN + n)*NN + tid + 256] = acc[1][h];
    }
}

// ------------------------------------------------ K3: fused logits GEMM + bias + softmax
// block: 16 n-rows x all 512 m for one head. grid(32, 12), 256 threads.
// thread: rowgroup rg = tid>>6 (4 rows), lane = tid&63 (4 m per 256-chunk).
__global__ __launch_bounds__(256) void logits_softmax_kernel() {
    __shared__ float Qs[16][32];
    __shared__ __align__(16) float Ks[32][256];
    __shared__ float redmx[16][2], redsm[16][2];
    int n0 = blockIdx.x * 16, h = blockIdx.y;
    int tid = threadIdx.x;
    int rg = tid >> 6, lane = tid & 63;
    int wh = lane >> 5;                      // warp-half within rowgroup
    for (int i = tid; i < 512; i += 256)
        Qs[i >> 5][i & 31] = g_qh[((size_t)h*NN + n0 + (i >> 5))*32 + (i & 31)];
    float acc[4][2][4];
    #pragma unroll
    for (int c = 0; c < 2; c++) {
        __syncthreads();
        for (int i = tid; i < 8192; i += 256)
            Ks[i >> 8][i & 255] = g_khT[((size_t)h*32 + (i >> 8))*NN + c*256 + (i & 255)];
        __syncthreads();
        #pragma unroll
        for (int r = 0; r < 4; r++) { acc[r][c][0]=0.f; acc[r][c][1]=0.f; acc[r][c][2]=0.f; acc[r][c][3]=0.f; }
        #pragma unroll
        for (int kk = 0; kk < 32; kk++) {
            float4 b = *(const float4*)&Ks[kk][lane*4];
            #pragma unroll
            for (int r = 0; r < 4; r++) {
                float q = Qs[rg*4 + r][kk];
                acc[r][c][0] += q*b.x; acc[r][c][1] += q*b.y;
                acc[r][c][2] += q*b.z; acc[r][c][3] += q*b.w;
            }
        }
    }
    // add bias (resident in g_attnT)
    #pragma unroll
    for (int r = 0; r < 4; r++)
        #pragma unroll
        for (int c = 0; c < 2; c++) {
            float4 bv = *(const float4*)&g_attnT[((size_t)h*NN + n0 + rg*4 + r)*NN + c*256 + lane*4];
            acc[r][c][0] += bv.x; acc[r][c][1] += bv.y; acc[r][c][2] += bv.z; acc[r][c][3] += bv.w;
        }
    // softmax per row over 64 lanes (2 warps)
    #pragma unroll
    for (int r = 0; r < 4; r++) {
        float mx = -1e30f;
        #pragma unroll
        for (int c = 0; c < 2; c++)
            #pragma unroll
            for (int j = 0; j < 4; j++) mx = fmaxf(mx, acc[r][c][j]);
        #pragma unroll
        for (int o = 16; o; o >>= 1) mx = fmaxf(mx, __shfl_xor_sync(0xffffffffu, mx, o));
        if ((lane & 31) == 0) redmx[rg*4 + r][wh] = mx;
    }
    __syncthreads();
    #pragma unroll
    for (int r = 0; r < 4; r++) {
        float mx = fmaxf(redmx[rg*4 + r][0], redmx[rg*4 + r][1]);
        float sm = 0.f;
        #pragma unroll
        for (int c = 0; c < 2; c++)
            #pragma unroll
            for (int j = 0; j < 4; j++) {
                float e = __expf(acc[r][c][j] - mx);
                acc[r][c][j] = e; sm += e;
            }
        #pragma unroll
        for (int o = 16; o; o >>= 1) sm += __shfl_xor_sync(0xffffffffu, sm, o);
        if ((lane & 31) == 0) redsm[rg*4 + r][wh] = sm;
    }
    __syncthreads();
    #pragma unroll
    for (int r = 0; r < 4; r++) {
        float inv = 1.f / (redsm[rg*4 + r][0] + redsm[rg*4 + r][1]);
        #pragma unroll
        for (int c = 0; c < 2; c++) {
            float4 st = make_float4(acc[r][c][0]*inv, acc[r][c][1]*inv, acc[r][c][2]*inv, acc[r][c][3]*inv);
            *(float4*)&g_attnT[((size_t)h*NN + n0 + rg*4 + r)*NN + c*256 + lane*4] = st;
        }
    }
}

// ------------------------------------------------ K4a: per-head attn @ [v|v_g]  (512x48x512)
__global__ __launch_bounds__(256) void outval_gemm() {
    __shared__ __align__(16) float As[32][68];
    __shared__ float Bs[32][48];
    int n0 = blockIdx.x * 64, h = blockIdx.y;
    int tid = threadIdx.x, tx = tid % 16, ty = tid / 16;
    float acc[4][3] = {};
    for (int kt = 0; kt < 16; kt++) {
        int kb = kt * 32;
        for (int i = tid; i < 2048; i += 256)
            As[i % 32][i / 32] = g_attnT[((size_t)h*NN + n0 + i/32)*NN + kb + (i % 32)];
        for (int i = tid; i < 1536; i += 256)
            Bs[i / 48][i % 48] = g_vpack[(size_t)(kb + i/48) * 576 + h*48 + (i % 48)];
        __syncthreads();
        #pragma unroll
        for (int kk = 0; kk < 32; kk++) {
            float4 a = *(const float4*)&As[kk][ty * 4];
            float b0 = Bs[kk][tx*3], b1 = Bs[kk][tx*3+1], b2 = Bs[kk][tx*3+2];
            acc[0][0] += a.x*b0; acc[0][1] += a.x*b1; acc[0][2] += a.x*b2;
            acc[1][0] += a.y*b0; acc[1][1] += a.y*b1; acc[1][2] += a.y*b2;
            acc[2][0] += a.z*b0; acc[2][1] += a.z*b1; acc[2][2] += a.z*b2;
            acc[3][0] += a.w*b0; acc[3][1] += a.w*b1; acc[3][2] += a.w*b2;
        }
        __syncthreads();
    }
    #pragma unroll
    for (int i = 0; i < 4; i++)
        #pragma unroll
        for (int j = 0; j < 3; j++)
            g_oval[(size_t)(n0 + ty*4 + i) * 576 + h*48 + tx*3 + j] = acc[i][j];
}

// ------------------------------------------------ K4b: pair_feat = attn @ z  per n
__global__ __launch_bounds__(256) void pairfeat_kernel(const float* __restrict__ z) {
    __shared__ float sm[12288];
    int n = blockIdx.x, tid = threadIdx.x;
    int c4 = tid & 31, mp = tid >> 5;
    for (int i = tid; i < 6144; i += 256)
        sm[i] = g_attnT[((size_t)(i/512)*NN + n)*NN + (i % 512)];
    __syncthreads();
    float acc[12][4] = {};
    const float4* z4 = (const float4*)z + (size_t)n * NN * 32;
    #pragma unroll 4
    for (int m = mp*64; m < mp*64 + 64; m++) {
        float4 zv = z4[(size_t)m * 32 + c4];
        #pragma unroll
        for (int h = 0; h < 12; h++) {
            float a = sm[h*512 + m];
            acc[h][0] += a*zv.x; acc[h][1] += a*zv.y; acc[h][2] += a*zv.z; acc[h][3] += a*zv.w;
        }
    }
    __syncthreads();
    #pragma unroll
    for (int h = 0; h < 12; h++)
        #pragma unroll
        for (int j = 0; j < 4; j++)
            sm[mp*1536 + h*128 + c4*4 + j] = acc[h][j];
    __syncthreads();
    for (int o = tid; o < 1536; o += 256) {
        float s = 0.f;
        #pragma unroll
        for (int p = 0; p < 8; p++) s += sm[p*1536 + o];
        int h = o >> 7, c = o & 127;
        g_feats[(size_t)n*FEAT + h*176 + 48 + c] = s;
    }
}

// ------------------------------------------------ K5: local frame + norms + scalar copy
__global__ void assemble_kernel(const float* __restrict__ trans, const float* __restrict__ rot) {
    int n = blockIdx.x, t = threadIdx.x;  // 288 threads
    __shared__ float R[9], T[3];
    if (t < 9) R[t] = rot[n*9 + t];
    if (t < 3) T[t] = trans[n*3 + t];
    __syncthreads();
    if (t < 96) {
        int h = t / 8, p = t % 8;
        const float* g = &g_oval[(size_t)n*576 + h*48 + 16 + p*3];
        float gx = g[0] - T[0], gy = g[1] - T[1], gz = g[2] - T[2];
        float lx = R[0]*gx + R[3]*gy + R[6]*gz;
        float ly = R[1]*gx + R[4]*gy + R[7]*gz;
        float lz = R[2]*gx + R[5]*gy + R[8]*gz;
        float* f = &g_feats[(size_t)n*FEAT + h*176];
        f[16 + p*3] = lx; f[16 + p*3 + 1] = ly; f[16 + p*3 + 2] = lz;
        f[40 + p] = sqrtf(lx*lx + ly*ly + lz*lz);
    } else if (t < 96 + 192) {
        int u = t - 96, h = u / 16, c = u % 16;
        g_feats[(size_t)n*FEAT + h*176 + c] = g_oval[(size_t)n*576 + h*48 + c];
    }
}

// ------------------------------------------------ K6: feats(512x2112) @ Wout(2112x384), split-K
__global__ __launch_bounds__(256) void final_gemm(const float* __restrict__ Wout) {
    __shared__ __align__(16) float As[32][68];
    __shared__ __align__(16) float Bs[32][68];
    int n0 = blockIdx.x * 64, c0 = blockIdx.y * 64, sp = blockIdx.z;
    int tid = threadIdx.x, tx = tid % 16, ty = tid / 16;
    int k0 = sp * 17, k1 = min(66, k0 + 17);
    float acc[4][4] = {};
    for (int kt = k0; kt < k1; kt++) {
        int kb = kt * 32;
        for (int i = tid; i < 2048; i += 256)
            As[i % 32][i / 32] = g_feats[(size_t)(n0 + i/32)*FEAT + kb + (i % 32)];
        for (int i = tid; i < 2048; i += 256)
            Bs[i / 64][i % 64] = Wout[(size_t)(kb + i/64)*CSd + c0 + (i % 64)];
        __syncthreads();
        #pragma unroll
        for (int kk = 0; kk < 32; kk++) {
            float4 a = *(const float4*)&As[kk][ty * 4];
            float4 b = *(const float4*)&Bs[kk][tx * 4];
            FMA16(acc, a, b);
        }
        __syncthreads();
    }
    #pragma unroll
    for (int i = 0; i < 4; i++)
        #pragma unroll
        for (int j = 0; j < 4; j++)
            g_part[(size_t)sp*NN*CSd + (n0 + ty*4 + i)*CSd + c0 + tx*4 + j] = acc[i][j];
}

__global__ void finalize_kernel(const float* __restrict__ bout, float* __restrict__ out) {
    int idx = blockIdx.x * blockDim.x + threadIdx.x;
    if (idx < NN * CSd) {
        int c = idx % CSd;
        out[idx] = bout[c] + g_part[idx] + g_part[NN*CSd + idx]
                 + g_part[2*NN*CSd + idx] + g_part[3*NN*CSd + idx];
    }
}

extern "C" void kernel_launch(void* const* d_in, const int* in_sizes, int n_in,
                              void* d_out, int out_size) {
    const float* s       = (const float*)d_in[0];
    const float* z       = (const float*)d_in[1];
    const float* trans   = (const float*)d_in[2];
    const float* rot     = (const float*)d_in[3];
    const float* Wq  = (const float*)d_in[5];  const float* bq  = (const float*)d_in[6];
    const float* Wk  = (const float*)d_in[7];  const float* bk  = (const float*)d_in[8];
    const float* Wv  = (const float*)d_in[9];  const float* bv  = (const float*)d_in[10];
    const float* Wqp = (const float*)d_in[11]; const float* bqp = (const float*)d_in[12];
    const float* Wkp = (const float*)d_in[13]; const float* bkp = (const float*)d_in[14];
    const float* Wvp = (const float*)d_in[15]; const float* bvp = (const float*)d_in[16];
    const float* Wb  = (const float*)d_in[17]; const float* bb  = (const float*)d_in[18];
    const float* dist_emb      = (const float*)d_in[19];
    const float* scale_logits  = (const float*)d_in[20];
    const float* head_weights  = (const float*)d_in[21];
    const float* Wout = (const float*)d_in[22];
    const float* bout = (const float*)d_in[23];
    float* out = (float*)d_out;

    pack_kernel<<<(CSd*PROJ + 255)/256, 256>>>(Wq,bq,Wk,bk,Wv,bv,Wqp,bqp,Wkp,bkp,Wvp,bvp);
    bias_kernel<<<NN, 256>>>(z, trans, Wb, bb, dist_emb, scale_logits);
    proj_gemm<<<dim3(8, 18), 256>>>(s);
    geom_kernel<<<NN, 128>>>(trans, rot, head_weights);
    logits_softmax_kernel<<<dim3(32, 12), 256>>>();
    outval_gemm<<<dim3(8, 12), 256>>>();
    pairfeat_kernel<<<NN, 256>>>(z);
    assemble_kernel<<<NN, 288>>>(trans, rot);
    final_gemm<<<dim3(8, 6, 4), 256>>>(Wout);
    finalize_kernel<<<(NN*CSd + 255)/256, 256>>>(bout, out);
}

// round 8
// speedup vs baseline: 1.4792x; 1.0505x over previous
#include <cuda_runtime.h>
#include <math.h>

#define NN 512
#define CSd 384
#define CZd 128
#define PROJ 1152
#define FEAT 2112

__device__ __align__(16) float g_Wcat[CSd * PROJ];
__device__ __align__(16) float g_bcat[PROJ];
__device__ __align__(16) float g_proj[NN * PROJ];
__device__ __align__(16) float g_qh[12 * NN * 32];
__device__ __align__(16) float g_khT[12 * 32 * NN];
__device__ __align__(16) float g_attnT[12 * NN * NN];   // bias -> attn (in place)
__device__ __align__(16) float g_vpack[NN * 576];
__device__ __align__(16) float g_oval[NN * 576];
__device__ __align__(16) float g_feats[NN * FEAT];
__device__ __align__(16) float g_part[4 * NN * CSd];

// ------------------------------------------------ K0: pack projection weights
__global__ void pack_kernel(const float* Wq, const float* bq, const float* Wk, const float* bk,
                            const float* Wv, const float* bv, const float* Wqp, const float* bqp,
                            const float* Wkp, const float* bkp, const float* Wvp, const float* bvp) {
    int idx = blockIdx.x * blockDim.x + threadIdx.x;
    if (idx < CSd * PROJ) {
        int r = idx / PROJ, gc = idx % PROJ;
        const float* W; int w, lc;
        if      (gc < 192) { W = Wq;  w = 192; lc = gc;       }
        else if (gc < 384) { W = Wk;  w = 192; lc = gc - 192; }
        else if (gc < 576) { W = Wv;  w = 192; lc = gc - 384; }
        else if (gc < 720) { W = Wqp; w = 144; lc = gc - 576; }
        else if (gc < 864) { W = Wkp; w = 144; lc = gc - 720; }
        else               { W = Wvp; w = 288; lc = gc - 864; }
        g_Wcat[idx] = W[r * w + lc];
    }
    if (idx < PROJ) {
        int gc = idx; const float* bp; int lc;
        if      (gc < 192) { bp = bq;  lc = gc;       }
        else if (gc < 384) { bp = bk;  lc = gc - 192; }
        else if (gc < 576) { bp = bv;  lc = gc - 384; }
        else if (gc < 720) { bp = bqp; lc = gc - 576; }
        else if (gc < 864) { bp = bkp; lc = gc - 720; }
        else               { bp = bvp; lc = gc - 864; }
        g_bcat[idx] = bp[lc];
    }
}

#define FMA16(acc, a, b) do { \
    acc[0][0] += a.x*b.x; acc[0][1] += a.x*b.y; acc[0][2] += a.x*b.z; acc[0][3] += a.x*b.w; \
    acc[1][0] += a.y*b.x; acc[1][1] += a.y*b.y; acc[1][2] += a.y*b.z; acc[1][3] += a.y*b.w; \
    acc[2][0] += a.z*b.x; acc[2][1] += a.z*b.y; acc[2][2] += a.z*b.z; acc[2][3] += a.z*b.w; \
    acc[3][0] += a.w*b.x; acc[3][1] += a.w*b.y; acc[3][2] += a.w*b.z; acc[3][3] += a.w*b.w; \
} while (0)

// ------------------------------------------------ K1: s(512x384) @ Wcat(384x1152) + b
__global__ __launch_bounds__(256) void proj_gemm(const float* __restrict__ sIn) {
    __shared__ __align__(16) float As[32][68];
    __shared__ __align__(16) float Bs[32][68];
    int n0 = blockIdx.x * 64, c0 = blockIdx.y * 64;
    int tid = threadIdx.x, tx = tid % 16, ty = tid / 16;
    float acc[4][4] = {};
    for (int kt = 0; kt < 12; kt++) {
        int kb = kt * 32;
        for (int i = tid; i < 2048; i += 256)
            As[i % 32][i / 32] = sIn[(n0 + i / 32) * CSd + kb + (i % 32)];
        for (int i = tid; i < 2048; i += 256)
            Bs[i / 64][i % 64] = g_Wcat[(kb + i / 64) * PROJ + c0 + (i % 64)];
        __syncthreads();
        #pragma unroll
        for (int kk = 0; kk < 32; kk++) {
            float4 a = *(const float4*)&As[kk][ty * 4];
            float4 b = *(const float4*)&Bs[kk][tx * 4];
            FMA16(acc, a, b);
        }
        __syncthreads();
    }
    #pragma unroll
    for (int i = 0; i < 4; i++) {
        int row = n0 + ty * 4 + i;
        #pragma unroll
        for (int j = 0; j < 4; j++) {
            int col = c0 + tx * 4 + j;
            g_proj[(size_t)row * PROJ + col] = acc[i][j] + g_bcat[col];
        }
    }
}

// ------------------------------------------------ K2: rigid transform + qh/khT pack + vpack
__global__ void geom_kernel(const float* __restrict__ trans, const float* __restrict__ rot,
                            const float* __restrict__ head_weights) {
    int n = blockIdx.x, t = threadIdx.x;   // 128 threads
    __shared__ float R[9], T[3], hws[12];
    __shared__ float sqg[144], skg[144], qsq[12], ksq[12];
    if (t < 9)  R[t] = rot[n * 9 + t];
    if (t < 3)  T[t] = trans[n * 3 + t];
    if (t < 12) hws[t] = head_weights[t];
    __syncthreads();
    const float* pr = g_proj + (size_t)n * PROJ;
    if (t < 48) {
        float x = pr[576 + t*3], y = pr[576 + t*3 + 1], zz = pr[576 + t*3 + 2];
        sqg[t*3]     = R[0]*x + R[1]*y + R[2]*zz + T[0];
        sqg[t*3 + 1] = R[3]*x + R[4]*y + R[5]*zz + T[1];
        sqg[t*3 + 2] = R[6]*x + R[7]*y + R[8]*zz + T[2];
    } else if (t < 96) {
        int u = t - 48;
        float x = pr[720 + u*3], y = pr[720 + u*3 + 1], zz = pr[720 + u*3 + 2];
        skg[u*3]     = R[0]*x + R[1]*y + R[2]*zz + T[0];
        skg[u*3 + 1] = R[3]*x + R[4]*y + R[5]*zz + T[1];
        skg[u*3 + 2] = R[6]*x + R[7]*y + R[8]*zz + T[2];
    }
    if (t < 96) {
        int h = t / 8, p = t % 8;
        float x = pr[864 + t*3], y = pr[864 + t*3 + 1], zz = pr[864 + t*3 + 2];
        float* vp = &g_vpack[(size_t)n*576 + h*48 + 16 + p*3];
        vp[0] = R[0]*x + R[1]*y + R[2]*zz + T[0];
        vp[1] = R[3]*x + R[4]*y + R[5]*zz + T[1];
        vp[2] = R[6]*x + R[7]*y + R[8]*zz + T[2];
    }
    __syncthreads();
    if (t < 12) {
        float sq = 0.f, sk = 0.f;
        #pragma unroll
        for (int j = 0; j < 12; j++) {
            float a = sqg[t*12 + j]; sq += a * a;
            float b = skg[t*12 + j]; sk += b * b;
        }
        qsq[t] = sq; ksq[t] = sk;
    }
    __syncthreads();
    for (int i = t; i < 384; i += 128) {
        int h = i / 32, c = i % 32;
        float hw = hws[h];
        float qv = 0.f, kv = 0.f;
        if (c < 16) {
            qv = 0.25f * pr[h*16 + c];
            kv = pr[192 + h*16 + c];
        } else if (c < 28) {
            qv = hw * sqg[h*12 + (c - 16)];
            kv = skg[h*12 + (c - 16)];
        } else if (c == 28) {
            qv = -0.5f * hw * qsq[h];
            kv = 1.f;
        } else if (c == 29) {
            qv = -0.5f * hw;
            kv = ksq[h];
        }
        g_qh[((size_t)h*NN + n)*32 + c] = qv;
        g_khT[((size_t)h*32 + c)*NN + n] = kv;
    }
    for (int i = t; i < 576; i += 128) {
        int h = i / 48, c = i % 48;
        if (c < 16)       g_vpack[(size_t)n*576 + i] = pr[384 + h*16 + c];
        else if (c >= 40) g_vpack[(size_t)n*576 + i] = 0.f;
    }
}

// ------------------------------------------------ K2b: bias -> g_attnT[h][n][m]
// flat GEMM over nm rows: block = 256 rows, grid 1024. Coalesced z loads via smem.
__global__ __launch_bounds__(256) void bias_kernel(const float* __restrict__ z,
        const float* __restrict__ trans, const float* __restrict__ Wb, const float* __restrict__ bb,
        const float* __restrict__ dist_emb, const float* __restrict__ scale_logits) {
    __shared__ __align__(16) float As[256][36];
    __shared__ __align__(16) float4 wT[12][32];
    __shared__ float des[64 * 12], phs[36], bbs[12];
    int nm0 = blockIdx.x * 256;
    int n = nm0 >> 9;
    int tid = threadIdx.x;
    for (int i = tid; i < 12 * 32; i += 256) {
        int h = i / 32, c4 = i % 32;
        wT[h][c4] = make_float4(Wb[(c4*4)*12 + h], Wb[(c4*4+1)*12 + h],
                                Wb[(c4*4+2)*12 + h], Wb[(c4*4+3)*12 + h]);
    }
    for (int i = tid; i < 768; i += 256) des[i] = dist_emb[i];
    if (tid < 12) {
        bbs[tid] = bb[tid];
        float e0 = expf(scale_logits[tid]), e1 = expf(scale_logits[12 + tid]), e2 = expf(scale_logits[24 + tid]);
        float inv = 1.f / (e0 + e1 + e2);
        phs[tid] = e0 * inv; phs[12 + tid] = e1 * inv; phs[24 + tid] = e2 * inv;
    }
    __syncthreads();
    // geometric bias for this thread's (n, m) pair
    int m = (nm0 & 511) + tid;
    float acc[12];
    {
        float dx = trans[n*3]   - trans[m*3];
        float dy = trans[n*3+1] - trans[m*3+1];
        float dz = trans[n*3+2] - trans[m*3+2];
        float d = sqrtf(dx*dx + dy*dy + dz*dz);
        int bin = max(0, min(63, (int)ceilf(d * 2.f) - 1));
        float w0 = (d <= 5.f) ? 1.f : 0.f;
        float w1 = (d > 5.f && d <= 15.f) ? 1.f : 0.f;
        #pragma unroll
        for (int h = 0; h < 12; h++)
            acc[h] = bbs[h] + des[bin*12 + h] + w0*phs[h] + w1*phs[12 + h] + phs[24 + h];
    }
    // z @ Wb, K=128 in 4 chunks of 32
    const float4* z4 = (const float4*)z;
    #pragma unroll 1
    for (int kc = 0; kc < 4; kc++) {
        __syncthreads();
        #pragma unroll
        for (int i = tid; i < 2048; i += 256) {
            int r = i >> 3, c4 = i & 7;
            *(float4*)&As[r][c4*4] = z4[((size_t)(nm0 + r))*32 + kc*8 + c4];
        }
        __syncthreads();
        #pragma unroll
        for (int c4 = 0; c4 < 8; c4++) {
            float4 zv = *(const float4*)&As[tid][c4*4];
            int cc = kc*8 + c4;
            #pragma unroll
            for (int h = 0; h < 12; h++) {
                float4 w = wT[h][cc];
                acc[h] += zv.x*w.x + zv.y*w.y + zv.z*w.z + zv.w*w.w;
            }
        }
    }
    #pragma unroll
    for (int h = 0; h < 12; h++)
        g_attnT[(size_t)h*NN*NN + nm0 + tid] = acc[h];
}

// ------------------------------------------------ K3: fused logits GEMM + bias + softmax
__global__ __launch_bounds__(256) void logits_softmax_kernel() {
    __shared__ float Qs[16][32];
    __shared__ __align__(16) float Ks[32][256];
    __shared__ float redmx[16][2], redsm[16][2];
    int n0 = blockIdx.x * 16, h = blockIdx.y;
    int tid = threadIdx.x;
    int rg = tid >> 6, lane = tid & 63;
    int wh = lane >> 5;
    for (int i = tid; i < 512; i += 256)
        Qs[i >> 5][i & 31] = g_qh[((size_t)h*NN + n0 + (i >> 5))*32 + (i & 31)];
    float acc[4][2][4];
    #pragma unroll
    for (int c = 0; c < 2; c++) {
        __syncthreads();
        for (int i = tid; i < 8192; i += 256)
            Ks[i >> 8][i & 255] = g_khT[((size_t)h*32 + (i >> 8))*NN + c*256 + (i & 255)];
        __syncthreads();
        #pragma unroll
        for (int r = 0; r < 4; r++) { acc[r][c][0]=0.f; acc[r][c][1]=0.f; acc[r][c][2]=0.f; acc[r][c][3]=0.f; }
        #pragma unroll
        for (int kk = 0; kk < 32; kk++) {
            float4 b = *(const float4*)&Ks[kk][lane*4];
            #pragma unroll
            for (int r = 0; r < 4; r++) {
                float q = Qs[rg*4 + r][kk];
                acc[r][c][0] += q*b.x; acc[r][c][1] += q*b.y;
                acc[r][c][2] += q*b.z; acc[r][c][3] += q*b.w;
            }
        }
    }
    #pragma unroll
    for (int r = 0; r < 4; r++)
        #pragma unroll
        for (int c = 0; c < 2; c++) {
            float4 bv = *(const float4*)&g_attnT[((size_t)h*NN + n0 + rg*4 + r)*NN + c*256 + lane*4];
            acc[r][c][0] += bv.x; acc[r][c][1] += bv.y; acc[r][c][2] += bv.z; acc[r][c][3] += bv.w;
        }
    #pragma unroll
    for (int r = 0; r < 4; r++) {
        float mx = -1e30f;
        #pragma unroll
        for (int c = 0; c < 2; c++)
            #pragma unroll
            for (int j = 0; j < 4; j++) mx = fmaxf(mx, acc[r][c][j]);
        #pragma unroll
        for (int o = 16; o; o >>= 1) mx = fmaxf(mx, __shfl_xor_sync(0xffffffffu, mx, o));
        if ((lane & 31) == 0) redmx[rg*4 + r][wh] = mx;
    }
    __syncthreads();
    #pragma unroll
    for (int r = 0; r < 4; r++) {
        float mx = fmaxf(redmx[rg*4 + r][0], redmx[rg*4 + r][1]);
        float sm = 0.f;
        #pragma unroll
        for (int c = 0; c < 2; c++)
            #pragma unroll
            for (int j = 0; j < 4; j++) {
                float e = __expf(acc[r][c][j] - mx);
                acc[r][c][j] = e; sm += e;
            }
        #pragma unroll
        for (int o = 16; o; o >>= 1) sm += __shfl_xor_sync(0xffffffffu, sm, o);
        if ((lane & 31) == 0) redsm[rg*4 + r][wh] = sm;
    }
    __syncthreads();
    #pragma unroll
    for (int r = 0; r < 4; r++) {
        float inv = 1.f / (redsm[rg*4 + r][0] + redsm[rg*4 + r][1]);
        #pragma unroll
        for (int c = 0; c < 2; c++) {
            float4 st = make_float4(acc[r][c][0]*inv, acc[r][c][1]*inv, acc[r][c][2]*inv, acc[r][c][3]*inv);
            *(float4*)&g_attnT[((size_t)h*NN + n0 + rg*4 + r)*NN + c*256 + lane*4] = st;
        }
    }
}

// ------------------------------------------------ K4a: per-head attn @ [v|v_g]  (512x48x512)
__global__ __launch_bounds__(256) void outval_gemm() {
    __shared__ __align__(16) float As[32][68];
    __shared__ float Bs[32][48];
    int n0 = blockIdx.x * 64, h = blockIdx.y;
    int tid = threadIdx.x, tx = tid % 16, ty = tid / 16;
    float acc[4][3] = {};
    for (int kt = 0; kt < 16; kt++) {
        int kb = kt * 32;
        for (int i = tid; i < 2048; i += 256)
            As[i % 32][i / 32] = g_attnT[((size_t)h*NN + n0 + i/32)*NN + kb + (i % 32)];
        for (int i = tid; i < 1536; i += 256)
            Bs[i / 48][i % 48] = g_vpack[(size_t)(kb + i/48) * 576 + h*48 + (i % 48)];
        __syncthreads();
        #pragma unroll
        for (int kk = 0; kk < 32; kk++) {
            float4 a = *(const float4*)&As[kk][ty * 4];
            float b0 = Bs[kk][tx*3], b1 = Bs[kk][tx*3+1], b2 = Bs[kk][tx*3+2];
            acc[0][0] += a.x*b0; acc[0][1] += a.x*b1; acc[0][2] += a.x*b2;
            acc[1][0] += a.y*b0; acc[1][1] += a.y*b1; acc[1][2] += a.y*b2;
            acc[2][0] += a.z*b0; acc[2][1] += a.z*b1; acc[2][2] += a.z*b2;
            acc[3][0] += a.w*b0; acc[3][1] += a.w*b1; acc[3][2] += a.w*b2;
        }
        __syncthreads();
    }
    #pragma unroll
    for (int i = 0; i < 4; i++)
        #pragma unroll
        for (int j = 0; j < 3; j++)
            g_oval[(size_t)(n0 + ty*4 + i) * 576 + h*48 + tx*3 + j] = acc[i][j];
}

// ------------------------------------------------ K4b: pair_feat = attn @ z  per n
__global__ __launch_bounds__(256) void pairfeat_kernel(const float* __restrict__ z) {
    __shared__ float sm[12288];
    int n = blockIdx.x, tid = threadIdx.x;
    int c4 = tid & 31, mp = tid >> 5;
    for (int i = tid; i < 6144; i += 256)
        sm[i] = g_attnT[((size_t)(i/512)*NN + n)*NN + (i % 512)];
    __syncthreads();
    float acc[12][4] = {};
    const float4* z4 = (const float4*)z + (size_t)n * NN * 32;
    #pragma unroll 4
    for (int m = mp*64; m < mp*64 + 64; m++) {
        float4 zv = z4[(size_t)m * 32 + c4];
        #pragma unroll
        for (int h = 0; h < 12; h++) {
            float a = sm[h*512 + m];
            acc[h][0] += a*zv.x; acc[h][1] += a*zv.y; acc[h][2] += a*zv.z; acc[h][3] += a*zv.w;
        }
    }
    __syncthreads();
    #pragma unroll
    for (int h = 0; h < 12; h++)
        #pragma unroll
        for (int j = 0; j < 4; j++)
            sm[mp*1536 + h*128 + c4*4 + j] = acc[h][j];
    __syncthreads();
    for (int o = tid; o < 1536; o += 256) {
        float s = 0.f;
        #pragma unroll
        for (int p = 0; p < 8; p++) s += sm[p*1536 + o];
        int h = o >> 7, c = o & 127;
        g_feats[(size_t)n*FEAT + h*176 + 48 + c] = s;
    }
}

// ------------------------------------------------ K5: local frame + norms + scalar copy
__global__ void assemble_kernel(const float* __restrict__ trans, const float* __restrict__ rot) {
    int n = blockIdx.x, t = threadIdx.x;  // 288 threads
    __shared__ float R[9], T[3];
    if (t < 9) R[t] = rot[n*9 + t];
    if (t < 3) T[t] = trans[n*3 + t];
    __syncthreads();
    if (t < 96) {
        int h = t / 8, p = t % 8;
        const float* g = &g_oval[(size_t)n*576 + h*48 + 16 + p*3];
        float gx = g[0] - T[0], gy = g[1] - T[1], gz = g[2] - T[2];
        float lx = R[0]*gx + R[3]*gy + R[6]*gz;
        float ly = R[1]*gx + R[4]*gy + R[7]*gz;
        float lz = R[2]*gx + R[5]*gy + R[8]*gz;
        float* f = &g_feats[(size_t)n*FEAT + h*176];
        f[16 + p*3] = lx; f[16 + p*3 + 1] = ly; f[16 + p*3 + 2] = lz;
        f[40 + p] = sqrtf(lx*lx + ly*ly + lz*lz);
    } else if (t < 96 + 192) {
        int u = t - 96, h = u / 16, c = u % 16;
        g_feats[(size_t)n*FEAT + h*176 + c] = g_oval[(size_t)n*576 + h*48 + c];
    }
}

// ------------------------------------------------ K6: feats(512x2112) @ Wout(2112x384), split-K
__global__ __launch_bounds__(256) void final_gemm(const float* __restrict__ Wout) {
    __shared__ __align__(16) float As[32][68];
    __shared__ __align__(16) float Bs[32][68];
    int n0 = blockIdx.x * 64, c0 = blockIdx.y * 64, sp = blockIdx.z;
    int tid = threadIdx.x, tx = tid % 16, ty = tid / 16;
    int k0 = sp * 17, k1 = min(66, k0 + 17);
    float acc[4][4] = {};
    for (int kt = k0; kt < k1; kt++) {
        int kb = kt * 32;
        for (int i = tid; i < 2048; i += 256)
            As[i % 32][i / 32] = g_feats[(size_t)(n0 + i/32)*FEAT + kb + (i % 32)];
        for (int i = tid; i < 2048; i += 256)
            Bs[i / 64][i % 64] = Wout[(size_t)(kb + i/64)*CSd + c0 + (i % 64)];
        __syncthreads();
        #pragma unroll
        for (int kk = 0; kk < 32; kk++) {
            float4 a = *(const float4*)&As[kk][ty * 4];
            float4 b = *(const float4*)&Bs[kk][tx * 4];
            FMA16(acc, a, b);
        }
        __syncthreads();
    }
    #pragma unroll
    for (int i = 0; i < 4; i++)
        #pragma unroll
        for (int j = 0; j < 4; j++)
            g_part[(size_t)sp*NN*CSd + (n0 + ty*4 + i)*CSd + c0 + tx*4 + j] = acc[i][j];
}

__global__ void finalize_kernel(const float* __restrict__ bout, float* __restrict__ out) {
    int idx = blockIdx.x * blockDim.x + threadIdx.x;
    if (idx < NN * CSd) {
        int c = idx % CSd;
        out[idx] = bout[c] + g_part[idx] + g_part[NN*CSd + idx]
                 + g_part[2*NN*CSd + idx] + g_part[3*NN*CSd + idx];
    }
}

extern "C" void kernel_launch(void* const* d_in, const int* in_sizes, int n_in,
                              void* d_out, int out_size) {
    const float* s       = (const float*)d_in[0];
    const float* z       = (const float*)d_in[1];
    const float* trans   = (const float*)d_in[2];
    const float* rot     = (const float*)d_in[3];
    const float* Wq  = (const float*)d_in[5];  const float* bq  = (const float*)d_in[6];
    const float* Wk  = (const float*)d_in[7];  const float* bk  = (const float*)d_in[8];
    const float* Wv  = (const float*)d_in[9];  const float* bv  = (const float*)d_in[10];
    const float* Wqp = (const float*)d_in[11]; const float* bqp = (const float*)d_in[12];
    const float* Wkp = (const float*)d_in[13]; const float* bkp = (const float*)d_in[14];
    const float* Wvp = (const float*)d_in[15]; const float* bvp = (const float*)d_in[16];
    const float* Wb  = (const float*)d_in[17]; const float* bb  = (const float*)d_in[18];
    const float* dist_emb      = (const float*)d_in[19];
    const float* scale_logits  = (const float*)d_in[20];
    const float* head_weights  = (const float*)d_in[21];
    const float* Wout = (const float*)d_in[22];
    const float* bout = (const float*)d_in[23];
    float* out = (float*)d_out;

    pack_kernel<<<(CSd*PROJ + 255)/256, 256>>>(Wq,bq,Wk,bk,Wv,bv,Wqp,bqp,Wkp,bkp,Wvp,bvp);
    bias_kernel<<<1024, 256>>>(z, trans, Wb, bb, dist_emb, scale_logits);
    proj_gemm<<<dim3(8, 18), 256>>>(s);
    geom_kernel<<<NN, 128>>>(trans, rot, head_weights);
    logits_softmax_kernel<<<dim3(32, 12), 256>>>();
    outval_gemm<<<dim3(8, 12), 256>>>();
    pairfeat_kernel<<<NN, 256>>>(z);
    assemble_kernel<<<NN, 288>>>(trans, rot);
    final_gemm<<<dim3(8, 6, 4), 256>>>(Wout);
    finalize_kernel<<<(NN*CSd + 255)/256, 256>>>(bout, out);
}

// round 10
// speedup vs baseline: 1.6416x; 1.1098x over previous
#include <cuda_runtime.h>
#include <math.h>

#define NN 512
#define CSd 384
#define CZd 128
#define PROJ 1152
#define FEAT 2112

__device__ __align__(16) float g_proj[NN * PROJ];
__device__ __align__(16) float g_qh[12 * NN * 32];
__device__ __align__(16) float g_khT[12 * 32 * NN];
__device__ __align__(16) float g_attnT[12 * NN * NN];   // bias -> attn (in place)
__device__ __align__(16) float g_vpack[NN * 576];
__device__ __align__(16) float g_oval[NN * 576];
__device__ __align__(16) float g_feats[NN * FEAT];
__device__ __align__(16) float g_part[4 * NN * CSd];

#define FMA16(acc, a, b) do { \
    acc[0][0] += a.x*b.x; acc[0][1] += a.x*b.y; acc[0][2] += a.x*b.z; acc[0][3] += a.x*b.w; \
    acc[1][0] += a.y*b.x; acc[1][1] += a.y*b.y; acc[1][2] += a.y*b.z; acc[1][3] += a.y*b.w; \
    acc[2][0] += a.z*b.x; acc[2][1] += a.z*b.y; acc[2][2] += a.z*b.z; acc[2][3] += a.z*b.w; \
    acc[3][0] += a.w*b.x; acc[3][1] += a.w*b.y; acc[3][2] += a.w*b.z; acc[3][3] += a.w*b.w; \
} while (0)

// piecewise weight/bias fetch for packed projection column layout
__device__ __forceinline__ float wcat_fetch(int r, int gc,
        const float* Wq, const float* Wk, const float* Wv,
        const float* Wqp, const float* Wkp, const float* Wvp) {
    if (gc < 192) return Wq [r*192 + gc];
    if (gc < 384) return Wk [r*192 + gc - 192];
    if (gc < 576) return Wv [r*192 + gc - 384];
    if (gc < 720) return Wqp[r*144 + gc - 576];
    if (gc < 864) return Wkp[r*144 + gc - 720];
    return Wvp[r*288 + gc - 864];
}
__device__ __forceinline__ float bcat_fetch(int gc,
        const float* bq, const float* bk, const float* bv,
        const float* bqp, const float* bkp, const float* bvp) {
    if (gc < 192) return bq [gc];
    if (gc < 384) return bk [gc - 192];
    if (gc < 576) return bv [gc - 384];
    if (gc < 720) return bqp[gc - 576];
    if (gc < 864) return bkp[gc - 720];
    return bvp[gc - 864];
}

// ================================================ K_mid: proj (blocks 0..143) + bias (blocks 144..1167)
__global__ __launch_bounds__(256) void mid_kernel(
        const float* __restrict__ sIn, const float* __restrict__ z,
        const float* __restrict__ trans, const float* __restrict__ Wb, const float* __restrict__ bb,
        const float* __restrict__ dist_emb, const float* __restrict__ scale_logits,
        const float* __restrict__ Wq, const float* __restrict__ bq,
        const float* __restrict__ Wk, const float* __restrict__ bk,
        const float* __restrict__ Wv, const float* __restrict__ bv,
        const float* __restrict__ Wqp, const float* __restrict__ bqp,
        const float* __restrict__ Wkp, const float* __restrict__ bkp,
        const float* __restrict__ Wvp, const float* __restrict__ bvp) {
    __shared__ union {
        struct { float As[32][68]; float Bs[32][68]; } p;
        struct { float As[256][36]; float4 wT[12][32]; float des[768]; float phs[36]; float bbs[12]; } b;
    } u;
    int tid = threadIdx.x;
    if (blockIdx.x < 144) {
        // ---------------- projection GEMM ----------------
        int bidx = blockIdx.x;
        int n0 = (bidx & 7) * 64, c0 = (bidx >> 3) * 64;
        int tx = tid % 16, ty = tid / 16;
        float acc[4][4] = {};
        for (int kt = 0; kt < 12; kt++) {
            int kb = kt * 32;
            for (int i = tid; i < 2048; i += 256)
                u.p.As[i % 32][i / 32] = sIn[(n0 + i / 32) * CSd + kb + (i % 32)];
            for (int i = tid; i < 2048; i += 256)
                u.p.Bs[i / 64][i % 64] = wcat_fetch(kb + i / 64, c0 + (i % 64), Wq, Wk, Wv, Wqp, Wkp, Wvp);
            __syncthreads();
            #pragma unroll
            for (int kk = 0; kk < 32; kk++) {
                float4 a = *(const float4*)&u.p.As[kk][ty * 4];
                float4 b = *(const float4*)&u.p.Bs[kk][tx * 4];
                FMA16(acc, a, b);
            }
            __syncthreads();
        }
        #pragma unroll
        for (int i = 0; i < 4; i++) {
            int row = n0 + ty * 4 + i;
            #pragma unroll
            for (int j = 0; j < 4; j++) {
                int col = c0 + tx * 4 + j;
                g_proj[(size_t)row * PROJ + col] = acc[i][j]
                    + bcat_fetch(col, bq, bk, bv, bqp, bkp, bvp);
            }
        }
    } else {
        // ---------------- bias GEMM ----------------
        int nm0 = (blockIdx.x - 144) * 256;
        int n = nm0 >> 9;
        for (int i = tid; i < 12 * 32; i += 256) {
            int h = i / 32, c4 = i % 32;
            u.b.wT[h][c4] = make_float4(Wb[(c4*4)*12 + h], Wb[(c4*4+1)*12 + h],
                                        Wb[(c4*4+2)*12 + h], Wb[(c4*4+3)*12 + h]);
        }
        for (int i = tid; i < 768; i += 256) u.b.des[i] = dist_emb[i];
        if (tid < 12) {
            u.b.bbs[tid] = bb[tid];
            float e0 = expf(scale_logits[tid]), e1 = expf(scale_logits[12 + tid]), e2 = expf(scale_logits[24 + tid]);
            float inv = 1.f / (e0 + e1 + e2);
            u.b.phs[tid] = e0 * inv; u.b.phs[12 + tid] = e1 * inv; u.b.phs[24 + tid] = e2 * inv;
        }
        __syncthreads();
        int m = (nm0 & 511) + tid;
        float acc[12];
        {
            float dx = trans[n*3]   - trans[m*3];
            float dy = trans[n*3+1] - trans[m*3+1];
            float dz = trans[n*3+2] - trans[m*3+2];
            float d = sqrtf(dx*dx + dy*dy + dz*dz);
            int bin = max(0, min(63, (int)ceilf(d * 2.f) - 1));
            float w0 = (d <= 5.f) ? 1.f : 0.f;
            float w1 = (d > 5.f && d <= 15.f) ? 1.f : 0.f;
            #pragma unroll
            for (int h = 0; h < 12; h++)
                acc[h] = u.b.bbs[h] + u.b.des[bin*12 + h] + w0*u.b.phs[h] + w1*u.b.phs[12 + h] + u.b.phs[24 + h];
        }
        const float4* z4 = (const float4*)z;
        #pragma unroll 1
        for (int kc = 0; kc < 4; kc++) {
            __syncthreads();
            #pragma unroll
            for (int i = tid; i < 2048; i += 256) {
                int r = i >> 3, c4 = i & 7;
                *(float4*)&u.b.As[r][c4*4] = z4[((size_t)(nm0 + r))*32 + kc*8 + c4];
            }
            __syncthreads();
            #pragma unroll
            for (int c4 = 0; c4 < 8; c4++) {
                float4 zv = *(const float4*)&u.b.As[tid][c4*4];
                int cc = kc*8 + c4;
                #pragma unroll
                for (int h = 0; h < 12; h++) {
                    float4 w = u.b.wT[h][cc];
                    acc[h] += zv.x*w.x + zv.y*w.y + zv.z*w.z + zv.w*w.w;
                }
            }
        }
        #pragma unroll
        for (int h = 0; h < 12; h++)
            g_attnT[(size_t)h*NN*NN + nm0 + tid] = acc[h];
    }
}

// ================================================ K2: rigid transform + qh/khT pack + vpack
__global__ void geom_kernel(const float* __restrict__ trans, const float* __restrict__ rot,
                            const float* __restrict__ head_weights) {
    int n = blockIdx.x, t = threadIdx.x;   // 128 threads
    __shared__ float R[9], T[3], hws[12];
    __shared__ float sqg[144], skg[144], qsq[12], ksq[12];
    if (t < 9)  R[t] = rot[n * 9 + t];
    if (t < 3)  T[t] = trans[n * 3 + t];
    if (t < 12) hws[t] = head_weights[t];
    __syncthreads();
    const float* pr = g_proj + (size_t)n * PROJ;
    if (t < 48) {
        float x = pr[576 + t*3], y = pr[576 + t*3 + 1], zz = pr[576 + t*3 + 2];
        sqg[t*3]     = R[0]*x + R[1]*y + R[2]*zz + T[0];
        sqg[t*3 + 1] = R[3]*x + R[4]*y + R[5]*zz + T[1];
        sqg[t*3 + 2] = R[6]*x + R[7]*y + R[8]*zz + T[2];
    } else if (t < 96) {
        int u = t - 48;
        float x = pr[720 + u*3], y = pr[720 + u*3 + 1], zz = pr[720 + u*3 + 2];
        skg[u*3]     = R[0]*x + R[1]*y + R[2]*zz + T[0];
        skg[u*3 + 1] = R[3]*x + R[4]*y + R[5]*zz + T[1];
        skg[u*3 + 2] = R[6]*x + R[7]*y + R[8]*zz + T[2];
    }
    if (t < 96) {
        int h = t / 8, p = t % 8;
        float x = pr[864 + t*3], y = pr[864 + t*3 + 1], zz = pr[864 + t*3 + 2];
        float* vp = &g_vpack[(size_t)n*576 + h*48 + 16 + p*3];
        vp[0] = R[0]*x + R[1]*y + R[2]*zz + T[0];
        vp[1] = R[3]*x + R[4]*y + R[5]*zz + T[1];
        vp[2] = R[6]*x + R[7]*y + R[8]*zz + T[2];
    }
    __syncthreads();
    if (t < 12) {
        float sq = 0.f, sk = 0.f;
        #pragma unroll
        for (int j = 0; j < 12; j++) {
            float a = sqg[t*12 + j]; sq += a * a;
            float b = skg[t*12 + j]; sk += b * b;
        }
        qsq[t] = sq; ksq[t] = sk;
    }
    __syncthreads();
    for (int i = t; i < 384; i += 128) {
        int h = i / 32, c = i % 32;
        float hw = hws[h];
        float qv = 0.f, kv = 0.f;
        if (c < 16) {
            qv = 0.25f * pr[h*16 + c];
            kv = pr[192 + h*16 + c];
        } else if (c < 28) {
            qv = hw * sqg[h*12 + (c - 16)];
            kv = skg[h*12 + (c - 16)];
        } else if (c == 28) {
            qv = -0.5f * hw * qsq[h];
            kv = 1.f;
        } else if (c == 29) {
            qv = -0.5f * hw;
            kv = ksq[h];
        }
        g_qh[((size_t)h*NN + n)*32 + c] = qv;
        g_khT[((size_t)h*32 + c)*NN + n] = kv;
    }
    for (int i = t; i < 576; i += 128) {
        int h = i / 48, c = i % 48;
        if (c < 16)       g_vpack[(size_t)n*576 + i] = pr[384 + h*16 + c];
        else if (c >= 40) g_vpack[(size_t)n*576 + i] = 0.f;
    }
}

// ================================================ K3: fused logits GEMM + bias + softmax
__global__ __launch_bounds__(256) void logits_softmax_kernel() {
    __shared__ float Qs[16][32];
    __shared__ __align__(16) float Ks[32][256];
    __shared__ float redmx[16][2], redsm[16][2];
    int n0 = blockIdx.x * 16, h = blockIdx.y;
    int tid = threadIdx.x;
    int rg = tid >> 6, lane = tid & 63;
    int wh = lane >> 5;
    for (int i = tid; i < 512; i += 256)
        Qs[i >> 5][i & 31] = g_qh[((size_t)h*NN + n0 + (i >> 5))*32 + (i & 31)];
    float acc[4][2][4];
    #pragma unroll
    for (int c = 0; c < 2; c++) {
        __syncthreads();
        for (int i = tid; i < 8192; i += 256)
            Ks[i >> 8][i & 255] = g_khT[((size_t)h*32 + (i >> 8))*NN + c*256 + (i & 255)];
        __syncthreads();
        #pragma unroll
        for (int r = 0; r < 4; r++) { acc[r][c][0]=0.f; acc[r][c][1]=0.f; acc[r][c][2]=0.f; acc[r][c][3]=0.f; }
        #pragma unroll
        for (int kk = 0; kk < 32; kk++) {
            float4 b = *(const float4*)&Ks[kk][lane*4];
            #pragma unroll
            for (int r = 0; r < 4; r++) {
                float q = Qs[rg*4 + r][kk];
                acc[r][c][0] += q*b.x; acc[r][c][1] += q*b.y;
                acc[r][c][2] += q*b.z; acc[r][c][3] += q*b.w;
            }
        }
    }
    #pragma unroll
    for (int r = 0; r < 4; r++)
        #pragma unroll
        for (int c = 0; c < 2; c++) {
            float4 bv = *(const float4*)&g_attnT[((size_t)h*NN + n0 + rg*4 + r)*NN + c*256 + lane*4];
            acc[r][c][0] += bv.x; acc[r][c][1] += bv.y; acc[r][c][2] += bv.z; acc[r][c][3] += bv.w;
        }
    #pragma unroll
    for (int r = 0; r < 4; r++) {
        float mx = -1e30f;
        #pragma unroll
        for (int c = 0; c < 2; c++)
            #pragma unroll
            for (int j = 0; j < 4; j++) mx = fmaxf(mx, acc[r][c][j]);
        #pragma unroll
        for (int o = 16; o; o >>= 1) mx = fmaxf(mx, __shfl_xor_sync(0xffffffffu, mx, o));
        if ((lane & 31) == 0) redmx[rg*4 + r][wh] = mx;
    }
    __syncthreads();
    #pragma unroll
    for (int r = 0; r < 4; r++) {
        float mx = fmaxf(redmx[rg*4 + r][0], redmx[rg*4 + r][1]);
        float sm = 0.f;
        #pragma unroll
        for (int c = 0; c < 2; c++)
            #pragma unroll
            for (int j = 0; j < 4; j++) {
                float e = __expf(acc[r][c][j] - mx);
                acc[r][c][j] = e; sm += e;
            }
        #pragma unroll
        for (int o = 16; o; o >>= 1) sm += __shfl_xor_sync(0xffffffffu, sm, o);
        if ((lane & 31) == 0) redsm[rg*4 + r][wh] = sm;
    }
    __syncthreads();
    #pragma unroll
    for (int r = 0; r < 4; r++) {
        float inv = 1.f / (redsm[rg*4 + r][0] + redsm[rg*4 + r][1]);
        #pragma unroll
        for (int c = 0; c < 2; c++) {
            float4 st = make_float4(acc[r][c][0]*inv, acc[r][c][1]*inv, acc[r][c][2]*inv, acc[r][c][3]*inv);
            *(float4*)&g_attnT[((size_t)h*NN + n0 + rg*4 + r)*NN + c*256 + lane*4] = st;
        }
    }
}

// ================================================ K_out: outval (blocks 0..95) + pairfeat (96..607)
__global__ __launch_bounds__(256) void out_kernel(const float* __restrict__ z) {
    __shared__ union {
        struct { float As[32][68]; float Bs[32][48]; } o;
        struct { float sm[12288]; } f;
    } u;
    int tid = threadIdx.x;
    if (blockIdx.x < 96) {
        // ---------------- attn @ [v|v_g] per head ----------------
        int n0 = (blockIdx.x & 7) * 64, h = blockIdx.x >> 3;
        int tx = tid % 16, ty = tid / 16;
        float acc[4][3] = {};
        for (int kt = 0; kt < 16; kt++) {
            int kb = kt * 32;
            for (int i = tid; i < 2048; i += 256)
                u.o.As[i % 32][i / 32] = g_attnT[((size_t)h*NN + n0 + i/32)*NN + kb + (i % 32)];
            for (int i = tid; i < 1536; i += 256)
                u.o.Bs[i / 48][i % 48] = g_vpack[(size_t)(kb + i/48) * 576 + h*48 + (i % 48)];
            __syncthreads();
            #pragma unroll
            for (int kk = 0; kk < 32; kk++) {
                float4 a = *(const float4*)&u.o.As[kk][ty * 4];
                float b0 = u.o.Bs[kk][tx*3], b1 = u.o.Bs[kk][tx*3+1], b2 = u.o.Bs[kk][tx*3+2];
                acc[0][0] += a.x*b0; acc[0][1] += a.x*b1; acc[0][2] += a.x*b2;
                acc[1][0] += a.y*b0; acc[1][1] += a.y*b1; acc[1][2] += a.y*b2;
                acc[2][0] += a.z*b0; acc[2][1] += a.z*b1; acc[2][2] += a.z*b2;
                acc[3][0] += a.w*b0; acc[3][1] += a.w*b1; acc[3][2] += a.w*b2;
            }
            __syncthreads();
        }
        #pragma unroll
        for (int i = 0; i < 4; i++)
            #pragma unroll
            for (int j = 0; j < 3; j++)
                g_oval[(size_t)(n0 + ty*4 + i) * 576 + h*48 + tx*3 + j] = acc[i][j];
    } else {
        // ---------------- pair_feat = attn @ z per n ----------------
        int n = blockIdx.x - 96;
        int c4 = tid & 31, mp = tid >> 5;
        for (int i = tid; i < 6144; i += 256)
            u.f.sm[i] = g_attnT[((size_t)(i/512)*NN + n)*NN + (i % 512)];
        __syncthreads();
        float acc[12][4] = {};
        const float4* z4 = (const float4*)z + (size_t)n * NN * 32;
        #pragma unroll 4
        for (int m = mp*64; m < mp*64 + 64; m++) {
            float4 zv = z4[(size_t)m * 32 + c4];
            #pragma unroll
            for (int h = 0; h < 12; h++) {
                float a = u.f.sm[h*512 + m];
                acc[h][0] += a*zv.x; acc[h][1] += a*zv.y; acc[h][2] += a*zv.z; acc[h][3] += a*zv.w;
            }
        }
        __syncthreads();
        #pragma unroll
        for (int h = 0; h < 12; h++)
            #pragma unroll
            for (int j = 0; j < 4; j++)
                u.f.sm[mp*1536 + h*128 + c4*4 + j] = acc[h][j];
        __syncthreads();
        for (int o = tid; o < 1536; o += 256) {
            float s = 0.f;
            #pragma unroll
            for (int p = 0; p < 8; p++) s += u.f.sm[p*1536 + o];
            int h = o >> 7, c = o & 127;
            g_feats[(size_t)n*FEAT + h*176 + 48 + c] = s;
        }
    }
}

// ================================================ K5: local frame + norms + scalar copy
__global__ void assemble_kernel(const float* __restrict__ trans, const float* __restrict__ rot) {
    int n = blockIdx.x, t = threadIdx.x;  // 288 threads
    __shared__ float R[9], T[3];
    if (t < 9) R[t] = rot[n*9 + t];
    if (t < 3) T[t] = trans[n*3 + t];
    __syncthreads();
    if (t < 96) {
        int h = t / 8, p = t % 8;
        const float* g = &g_oval[(size_t)n*576 + h*48 + 16 + p*3];
        float gx = g[0] - T[0], gy = g[1] - T[1], gz = g[2] - T[2];
        float lx = R[0]*gx + R[3]*gy + R[6]*gz;
        float ly = R[1]*gx + R[4]*gy + R[7]*gz;
        float lz = R[2]*gx + R[5]*gy + R[8]*gz;
        float* f = &g_feats[(size_t)n*FEAT + h*176];
        f[16 + p*3] = lx; f[16 + p*3 + 1] = ly; f[16 + p*3 + 2] = lz;
        f[40 + p] = sqrtf(lx*lx + ly*ly + lz*lz);
    } else if (t < 96 + 192) {
        int u = t - 96, h = u / 16, c = u % 16;
        g_feats[(size_t)n*FEAT + h*176 + c] = g_oval[(size_t)n*576 + h*48 + c];
    }
}

// ================================================ K6: feats(512x2112) @ Wout(2112x384), split-K
__global__ __launch_bounds__(256) void final_gemm(const float* __restrict__ Wout) {
    __shared__ __align__(16) float As[32][68];
    __shared__ __align__(16) float Bs[32][68];
    int n0 = blockIdx.x * 64, c0 = blockIdx.y * 64, sp = blockIdx.z;
    int tid = threadIdx.x, tx = tid % 16, ty = tid / 16;
    int k0 = sp * 17, k1 = min(66, k0 + 17);
    float acc[4][4] = {};
    for (int kt = k0; kt < k1; kt++) {
        int kb = kt * 32;
        for (int i = tid; i < 2048; i += 256)
            As[i % 32][i / 32] = g_feats[(size_t)(n0 + i/32)*FEAT + kb + (i % 32)];
        for (int i = tid; i < 2048; i += 256)
            Bs[i / 64][i % 64] = Wout[(size_t)(kb + i/64)*CSd + c0 + (i % 64)];
        __syncthreads();
        #pragma unroll
        for (int kk = 0; kk < 32; kk++) {
            float4 a = *(const float4*)&As[kk][ty * 4];
            float4 b = *(const float4*)&Bs[kk][tx * 4];
            FMA16(acc, a, b);
        }
        __syncthreads();
    }
    #pragma unroll
    for (int i = 0; i < 4; i++)
        #pragma unroll
        for (int j = 0; j < 4; j++)
            g_part[(size_t)sp*NN*CSd + (n0 + ty*4 + i)*CSd + c0 + tx*4 + j] = acc[i][j];
}

__global__ void finalize_kernel(const float* __restrict__ bout, float* __restrict__ out) {
    int idx = blockIdx.x * blockDim.x + threadIdx.x;
    if (idx < NN * CSd) {
        int c = idx % CSd;
        out[idx] = bout[c] + g_part[idx] + g_part[NN*CSd + idx]
                 + g_part[2*NN*CSd + idx] + g_part[3*NN*CSd + idx];
    }
}

extern "C" void kernel_launch(void* const* d_in, const int* in_sizes, int n_in,
                              void* d_out, int out_size) {
    const float* s       = (const float*)d_in[0];
    const float* z       = (const float*)d_in[1];
    const float* trans   = (const float*)d_in[2];
    const float* rot     = (const float*)d_in[3];
    const float* Wq  = (const float*)d_in[5];  const float* bq  = (const float*)d_in[6];
    const float* Wk  = (const float*)d_in[7];  const float* bk  = (const float*)d_in[8];
    const float* Wv  = (const float*)d_in[9];  const float* bv  = (const float*)d_in[10];
    const float* Wqp = (const float*)d_in[11]; const float* bqp = (const float*)d_in[12];
    const float* Wkp = (const float*)d_in[13]; const float* bkp = (const float*)d_in[14];
    const float* Wvp = (const float*)d_in[15]; const float* bvp = (const float*)d_in[16];
    const float* Wb  = (const float*)d_in[17]; const float* bb  = (const float*)d_in[18];
    const float* dist_emb      = (const float*)d_in[19];
    const float* scale_logits  = (const float*)d_in[20];
    const float* head_weights  = (const float*)d_in[21];
    const float* Wout = (const float*)d_in[22];
    const float* bout = (const float*)d_in[23];
    float* out = (float*)d_out;

    mid_kernel<<<1168, 256>>>(s, z, trans, Wb, bb, dist_emb, scale_logits,
                              Wq, bq, Wk, bk, Wv, bv, Wqp, bqp, Wkp, bkp, Wvp, bvp);
    geom_kernel<<<NN, 128>>>(trans, rot, head_weights);
    logits_softmax_kernel<<<dim3(32, 12), 256>>>();
    out_kernel<<<608, 256>>>(z);
    assemble_kernel<<<NN, 288>>>(trans, rot);
    final_gemm<<<dim3(8, 6, 4), 256>>>(Wout);
    finalize_kernel<<<(NN*CSd + 255)/256, 256>>>(bout, out);
}

// round 11
// speedup vs baseline: 1.6893x; 1.0291x over previous
#include <cuda_runtime.h>
#include <math.h>

#define NN 512
#define CSd 384
#define CZd 128
#define PROJ 1152
#define FEAT 2112

__device__ __align__(16) float g_proj[NN * PROJ];
__device__ __align__(16) float g_qh[12 * NN * 32];
__device__ __align__(16) float g_khT[12 * 32 * NN];
__device__ __align__(16) float g_attnT[12 * NN * NN];   // bias -> attn (in place)
__device__ __align__(16) float g_vpack[NN * 576];
__device__ __align__(16) float g_oval[NN * 576];
__device__ __align__(16) float g_feats[NN * FEAT];
__device__ __align__(16) float g_part[4 * NN * CSd];

#define FMA16(acc, a, b) do { \
    acc[0][0] += a.x*b.x; acc[0][1] += a.x*b.y; acc[0][2] += a.x*b.z; acc[0][3] += a.x*b.w; \
    acc[1][0] += a.y*b.x; acc[1][1] += a.y*b.y; acc[1][2] += a.y*b.z; acc[1][3] += a.y*b.w; \
    acc[2][0] += a.z*b.x; acc[2][1] += a.z*b.y; acc[2][2] += a.z*b.z; acc[2][3] += a.z*b.w; \
    acc[3][0] += a.w*b.x; acc[3][1] += a.w*b.y; acc[3][2] += a.w*b.z; acc[3][3] += a.w*b.w; \
} while (0)

__device__ __forceinline__ float wcat_fetch(int r, int gc,
        const float* Wq, const float* Wk, const float* Wv,
        const float* Wqp, const float* Wkp, const float* Wvp) {
    if (gc < 192) return Wq [r*192 + gc];
    if (gc < 384) return Wk [r*192 + gc - 192];
    if (gc < 576) return Wv [r*192 + gc - 384];
    if (gc < 720) return Wqp[r*144 + gc - 576];
    if (gc < 864) return Wkp[r*144 + gc - 720];
    return Wvp[r*288 + gc - 864];
}
__device__ __forceinline__ float bcat_fetch(int gc,
        const float* bq, const float* bk, const float* bv,
        const float* bqp, const float* bkp, const float* bvp) {
    if (gc < 192) return bq [gc];
    if (gc < 384) return bk [gc - 192];
    if (gc < 576) return bv [gc - 384];
    if (gc < 720) return bqp[gc - 576];
    if (gc < 864) return bkp[gc - 720];
    return bvp[gc - 864];
}

// ================================================ K_mid: proj (blocks 0..143) + bias (blocks 144..1167)
__global__ __launch_bounds__(256, 4) void mid_kernel(
        const float* __restrict__ sIn, const float* __restrict__ z,
        const float* __restrict__ trans, const float* __restrict__ Wb, const float* __restrict__ bb,
        const float* __restrict__ dist_emb, const float* __restrict__ scale_logits,
        const float* __restrict__ Wq, const float* __restrict__ bq,
        const float* __restrict__ Wk, const float* __restrict__ bk,
        const float* __restrict__ Wv, const float* __restrict__ bv,
        const float* __restrict__ Wqp, const float* __restrict__ bqp,
        const float* __restrict__ Wkp, const float* __restrict__ bkp,
        const float* __restrict__ Wvp, const float* __restrict__ bvp) {
    __shared__ union {
        struct { float As[32][68]; float Bs[32][68]; } p;
        struct { float As[256][36]; float4 wT[12][32]; float des[768]; float phs[36]; float bbs[12]; } b;
    } u;
    int tid = threadIdx.x;
    if (blockIdx.x < 144) {
        int bidx = blockIdx.x;
        int n0 = (bidx & 7) * 64, c0 = (bidx >> 3) * 64;
        int tx = tid % 16, ty = tid / 16;
        float acc[4][4] = {};
        for (int kt = 0; kt < 12; kt++) {
            int kb = kt * 32;
            for (int i = tid; i < 2048; i += 256)
                u.p.As[i % 32][i / 32] = sIn[(n0 + i / 32) * CSd + kb + (i % 32)];
            for (int i = tid; i < 2048; i += 256)
                u.p.Bs[i / 64][i % 64] = wcat_fetch(kb + i / 64, c0 + (i % 64), Wq, Wk, Wv, Wqp, Wkp, Wvp);
            __syncthreads();
            #pragma unroll
            for (int kk = 0; kk < 32; kk++) {
                float4 a = *(const float4*)&u.p.As[kk][ty * 4];
                float4 b = *(const float4*)&u.p.Bs[kk][tx * 4];
                FMA16(acc, a, b);
            }
            __syncthreads();
        }
        #pragma unroll
        for (int i = 0; i < 4; i++) {
            int row = n0 + ty * 4 + i;
            #pragma unroll
            for (int j = 0; j < 4; j++) {
                int col = c0 + tx * 4 + j;
                g_proj[(size_t)row * PROJ + col] = acc[i][j]
                    + bcat_fetch(col, bq, bk, bv, bqp, bkp, bvp);
            }
        }
    } else {
        int nm0 = (blockIdx.x - 144) * 256;
        int n = nm0 >> 9;
        for (int i = tid; i < 12 * 32; i += 256) {
            int h = i / 32, c4 = i % 32;
            u.b.wT[h][c4] = make_float4(Wb[(c4*4)*12 + h], Wb[(c4*4+1)*12 + h],
                                        Wb[(c4*4+2)*12 + h], Wb[(c4*4+3)*12 + h]);
        }
        for (int i = tid; i < 768; i += 256) u.b.des[i] = dist_emb[i];
        if (tid < 12) {
            u.b.bbs[tid] = bb[tid];
            float e0 = expf(scale_logits[tid]), e1 = expf(scale_logits[12 + tid]), e2 = expf(scale_logits[24 + tid]);
            float inv = 1.f / (e0 + e1 + e2);
            u.b.phs[tid] = e0 * inv; u.b.phs[12 + tid] = e1 * inv; u.b.phs[24 + tid] = e2 * inv;
        }
        __syncthreads();
        int m = (nm0 & 511) + tid;
        float acc[12];
        {
            float dx = trans[n*3]   - trans[m*3];
            float dy = trans[n*3+1] - trans[m*3+1];
            float dz = trans[n*3+2] - trans[m*3+2];
            float d = sqrtf(dx*dx + dy*dy + dz*dz);
            int bin = max(0, min(63, (int)ceilf(d * 2.f) - 1));
            float w0 = (d <= 5.f) ? 1.f : 0.f;
            float w1 = (d > 5.f && d <= 15.f) ? 1.f : 0.f;
            #pragma unroll
            for (int h = 0; h < 12; h++)
                acc[h] = u.b.bbs[h] + u.b.des[bin*12 + h] + w0*u.b.phs[h] + w1*u.b.phs[12 + h] + u.b.phs[24 + h];
        }
        const float4* z4 = (const float4*)z;
        #pragma unroll 1
        for (int kc = 0; kc < 4; kc++) {
            __syncthreads();
            #pragma unroll
            for (int i = tid; i < 2048; i += 256) {
                int r = i >> 3, c4 = i & 7;
                *(float4*)&u.b.As[r][c4*4] = z4[((size_t)(nm0 + r))*32 + kc*8 + c4];
            }
            __syncthreads();
            #pragma unroll
            for (int c4 = 0; c4 < 8; c4++) {
                float4 zv = *(const float4*)&u.b.As[tid][c4*4];
                int cc = kc*8 + c4;
                #pragma unroll
                for (int h = 0; h < 12; h++) {
                    float4 w = u.b.wT[h][cc];
                    acc[h] += zv.x*w.x + zv.y*w.y + zv.z*w.z + zv.w*w.w;
                }
            }
        }
        #pragma unroll
        for (int h = 0; h < 12; h++)
            g_attnT[(size_t)h*NN*NN + nm0 + tid] = acc[h];
    }
}

// ================================================ K2: rigid transform + qh/khT pack + vpack
__global__ void geom_kernel(const float* __restrict__ trans, const float* __restrict__ rot,
                            const float* __restrict__ head_weights) {
    int n = blockIdx.x, t = threadIdx.x;   // 128 threads
    __shared__ float R[9], T[3], hws[12];
    __shared__ float sqg[144], skg[144], qsq[12], ksq[12];
    if (t < 9)  R[t] = rot[n * 9 + t];
    if (t < 3)  T[t] = trans[n * 3 + t];
    if (t < 12) hws[t] = head_weights[t];
    __syncthreads();
    const float* pr = g_proj + (size_t)n * PROJ;
    if (t < 48) {
        float x = pr[576 + t*3], y = pr[576 + t*3 + 1], zz = pr[576 + t*3 + 2];
        sqg[t*3]     = R[0]*x + R[1]*y + R[2]*zz + T[0];
        sqg[t*3 + 1] = R[3]*x + R[4]*y + R[5]*zz + T[1];
        sqg[t*3 + 2] = R[6]*x + R[7]*y + R[8]*zz + T[2];
    } else if (t < 96) {
        int u = t - 48;
        float x = pr[720 + u*3], y = pr[720 + u*3 + 1], zz = pr[720 + u*3 + 2];
        skg[u*3]     = R[0]*x + R[1]*y + R[2]*zz + T[0];
        skg[u*3 + 1] = R[3]*x + R[4]*y + R[5]*zz + T[1];
        skg[u*3 + 2] = R[6]*x + R[7]*y + R[8]*zz + T[2];
    }
    if (t < 96) {
        int h = t / 8, p = t % 8;
        float x = pr[864 + t*3], y = pr[864 + t*3 + 1], zz = pr[864 + t*3 + 2];
        float* vp = &g_vpack[(size_t)n*576 + h*48 + 16 + p*3];
        vp[0] = R[0]*x + R[1]*y + R[2]*zz + T[0];
        vp[1] = R[3]*x + R[4]*y + R[5]*zz + T[1];
        vp[2] = R[6]*x + R[7]*y + R[8]*zz + T[2];
    }
    __syncthreads();
    if (t < 12) {
        float sq = 0.f, sk = 0.f;
        #pragma unroll
        for (int j = 0; j < 12; j++) {
            float a = sqg[t*12 + j]; sq += a * a;
            float b = skg[t*12 + j]; sk += b * b;
        }
        qsq[t] = sq; ksq[t] = sk;
    }
    __syncthreads();
    for (int i = t; i < 384; i += 128) {
        int h = i / 32, c = i % 32;
        float hw = hws[h];
        float qv = 0.f, kv = 0.f;
        if (c < 16) {
            qv = 0.25f * pr[h*16 + c];
            kv = pr[192 + h*16 + c];
        } else if (c < 28) {
            qv = hw * sqg[h*12 + (c - 16)];
            kv = skg[h*12 + (c - 16)];
        } else if (c == 28) {
            qv = -0.5f * hw * qsq[h];
            kv = 1.f;
        } else if (c == 29) {
            qv = -0.5f * hw;
            kv = ksq[h];
        }
        g_qh[((size_t)h*NN + n)*32 + c] = qv;
        g_khT[((size_t)h*32 + c)*NN + n] = kv;
    }
    for (int i = t; i < 576; i += 128) {
        int h = i / 48, c = i % 48;
        if (c < 16)       g_vpack[(size_t)n*576 + i] = pr[384 + h*16 + c];
        else if (c >= 40) g_vpack[(size_t)n*576 + i] = 0.f;
    }
}

// ================================================ K3: fused logits GEMM + bias + softmax
__global__ __launch_bounds__(256, 4) void logits_softmax_kernel() {
    __shared__ float Qs[16][32];
    __shared__ __align__(16) float Ks[32][256];
    __shared__ float redmx[16][2], redsm[16][2];
    int n0 = blockIdx.x * 16, h = blockIdx.y;
    int tid = threadIdx.x;
    int rg = tid >> 6, lane = tid & 63;
    int wh = lane >> 5;
    for (int i = tid; i < 512; i += 256)
        Qs[i >> 5][i & 31] = g_qh[((size_t)h*NN + n0 + (i >> 5))*32 + (i & 31)];
    float acc[4][2][4];
    #pragma unroll
    for (int c = 0; c < 2; c++) {
        __syncthreads();
        for (int i = tid; i < 8192; i += 256)
            Ks[i >> 8][i & 255] = g_khT[((size_t)h*32 + (i >> 8))*NN + c*256 + (i & 255)];
        __syncthreads();
        #pragma unroll
        for (int r = 0; r < 4; r++) { acc[r][c][0]=0.f; acc[r][c][1]=0.f; acc[r][c][2]=0.f; acc[r][c][3]=0.f; }
        #pragma unroll
        for (int kk = 0; kk < 32; kk++) {
            float4 b = *(const float4*)&Ks[kk][lane*4];
            #pragma unroll
            for (int r = 0; r < 4; r++) {
                float q = Qs[rg*4 + r][kk];
                acc[r][c][0] += q*b.x; acc[r][c][1] += q*b.y;
                acc[r][c][2] += q*b.z; acc[r][c][3] += q*b.w;
            }
        }
    }
    #pragma unroll
    for (int r = 0; r < 4; r++)
        #pragma unroll
        for (int c = 0; c < 2; c++) {
            float4 bv = *(const float4*)&g_attnT[((size_t)h*NN + n0 + rg*4 + r)*NN + c*256 + lane*4];
            acc[r][c][0] += bv.x; acc[r][c][1] += bv.y; acc[r][c][2] += bv.z; acc[r][c][3] += bv.w;
        }
    #pragma unroll
    for (int r = 0; r < 4; r++) {
        float mx = -1e30f;
        #pragma unroll
        for (int c = 0; c < 2; c++)
            #pragma unroll
            for (int j = 0; j < 4; j++) mx = fmaxf(mx, acc[r][c][j]);
        #pragma unroll
        for (int o = 16; o; o >>= 1) mx = fmaxf(mx, __shfl_xor_sync(0xffffffffu, mx, o));
        if ((lane & 31) == 0) redmx[rg*4 + r][wh] = mx;
    }
    __syncthreads();
    #pragma unroll
    for (int r = 0; r < 4; r++) {
        float mx = fmaxf(redmx[rg*4 + r][0], redmx[rg*4 + r][1]);
        float sm = 0.f;
        #pragma unroll
        for (int c = 0; c < 2; c++)
            #pragma unroll
            for (int j = 0; j < 4; j++) {
                float e = __expf(acc[r][c][j] - mx);
                acc[r][c][j] = e; sm += e;
            }
        #pragma unroll
        for (int o = 16; o; o >>= 1) sm += __shfl_xor_sync(0xffffffffu, sm, o);
        if ((lane & 31) == 0) redsm[rg*4 + r][wh] = sm;
    }
    __syncthreads();
    #pragma unroll
    for (int r = 0; r < 4; r++) {
        float inv = 1.f / (redsm[rg*4 + r][0] + redsm[rg*4 + r][1]);
        #pragma unroll
        for (int c = 0; c < 2; c++) {
            float4 st = make_float4(acc[r][c][0]*inv, acc[r][c][1]*inv, acc[r][c][2]*inv, acc[r][c][3]*inv);
            *(float4*)&g_attnT[((size_t)h*NN + n0 + rg*4 + r)*NN + c*256 + lane*4] = st;
        }
    }
}

// ================================================ K_out: outval (blocks 0..95) + pairfeat (96..607)
__global__ __launch_bounds__(256, 3) void out_kernel(const float* __restrict__ z) {
    __shared__ union {
        struct { float As[32][68]; float Bs[32][48]; } o;
        struct { float sm[6144]; } f;          // attn rows, then 2-stage reduction buffer
    } u;
    int tid = threadIdx.x;
    if (blockIdx.x < 96) {
        // ---------------- attn @ [v|v_g] per head ----------------
        int n0 = (blockIdx.x & 7) * 64, h = blockIdx.x >> 3;
        int tx = tid % 16, ty = tid / 16;
        float acc[4][3] = {};
        for (int kt = 0; kt < 16; kt++) {
            int kb = kt * 32;
            for (int i = tid; i < 2048; i += 256)
                u.o.As[i % 32][i / 32] = g_attnT[((size_t)h*NN + n0 + i/32)*NN + kb + (i % 32)];
            for (int i = tid; i < 1536; i += 256)
                u.o.Bs[i / 48][i % 48] = g_vpack[(size_t)(kb + i/48) * 576 + h*48 + (i % 48)];
            __syncthreads();
            #pragma unroll
            for (int kk = 0; kk < 32; kk++) {
                float4 a = *(const float4*)&u.o.As[kk][ty * 4];
                float b0 = u.o.Bs[kk][tx*3], b1 = u.o.Bs[kk][tx*3+1], b2 = u.o.Bs[kk][tx*3+2];
                acc[0][0] += a.x*b0; acc[0][1] += a.x*b1; acc[0][2] += a.x*b2;
                acc[1][0] += a.y*b0; acc[1][1] += a.y*b1; acc[1][2] += a.y*b2;
                acc[2][0] += a.z*b0; acc[2][1] += a.z*b1; acc[2][2] += a.z*b2;
                acc[3][0] += a.w*b0; acc[3][1] += a.w*b1; acc[3][2] += a.w*b2;
            }
            __syncthreads();
        }
        #pragma unroll
        for (int i = 0; i < 4; i++)
            #pragma unroll
            for (int j = 0; j < 3; j++)
                g_oval[(size_t)(n0 + ty*4 + i) * 576 + h*48 + tx*3 + j] = acc[i][j];
    } else {
        // ---------------- pair_feat = attn @ z per n ----------------
        int n = blockIdx.x - 96;
        int c4 = tid & 31, mp = tid >> 5;      // 8 m-partitions of 64
        for (int i = tid; i < 6144; i += 256)
            u.f.sm[i] = g_attnT[((size_t)(i/512)*NN + n)*NN + (i % 512)];
        __syncthreads();
        float acc[12][4] = {};
        const float4* z4 = (const float4*)z + (size_t)n * NN * 32;
        #pragma unroll 4
        for (int m = mp*64; m < mp*64 + 64; m++) {
            float4 zv = z4[(size_t)m * 32 + c4];
            #pragma unroll
            for (int h = 0; h < 12; h++) {
                float a = u.f.sm[h*512 + m];
                acc[h][0] += a*zv.x; acc[h][1] += a*zv.y; acc[h][2] += a*zv.z; acc[h][3] += a*zv.w;
            }
        }
        __syncthreads();   // all attn reads done; sm reusable
        if (mp >= 4) {
            #pragma unroll
            for (int h = 0; h < 12; h++)
                #pragma unroll
                for (int j = 0; j < 4; j++)
                    u.f.sm[(mp-4)*1536 + h*128 + c4*4 + j] = acc[h][j];
        }
        __syncthreads();
        if (mp < 4) {
            #pragma unroll
            for (int h = 0; h < 12; h++)
                #pragma unroll
                for (int j = 0; j < 4; j++) {
                    int o = mp*1536 + h*128 + c4*4 + j;
                    u.f.sm[o] += acc[h][j];     // read-modify-write own slot only
                }
        }
        __syncthreads();
        for (int o = tid; o < 1536; o += 256) {
            float s = u.f.sm[o] + u.f.sm[1536 + o] + u.f.sm[3072 + o] + u.f.sm[4608 + o];
            int h = o >> 7, c = o & 127;
            g_feats[(size_t)n*FEAT + h*176 + 48 + c] = s;
        }
    }
}

// ================================================ K5: local frame + norms + scalar copy
__global__ void assemble_kernel(const float* __restrict__ trans, const float* __restrict__ rot) {
    int n = blockIdx.x, t = threadIdx.x;  // 288 threads
    __shared__ float R[9], T[3];
    if (t < 9) R[t] = rot[n*9 + t];
    if (t < 3) T[t] = trans[n*3 + t];
    __syncthreads();
    if (t < 96) {
        int h = t / 8, p = t % 8;
        const float* g = &g_oval[(size_t)n*576 + h*48 + 16 + p*3];
        float gx = g[0] - T[0], gy = g[1] - T[1], gz = g[2] - T[2];
        float lx = R[0]*gx + R[3]*gy + R[6]*gz;
        float ly = R[1]*gx + R[4]*gy + R[7]*gz;
        float lz = R[2]*gx + R[5]*gy + R[8]*gz;
        float* f = &g_feats[(size_t)n*FEAT + h*176];
        f[16 + p*3] = lx; f[16 + p*3 + 1] = ly; f[16 + p*3 + 2] = lz;
        f[40 + p] = sqrtf(lx*lx + ly*ly + lz*lz);
    } else if (t < 96 + 192) {
        int u = t - 96, h = u / 16, c = u % 16;
        g_feats[(size_t)n*FEAT + h*176 + c] = g_oval[(size_t)n*576 + h*48 + c];
    }
}

// ================================================ K6: feats(512x2112) @ Wout(2112x384), split-K
__global__ __launch_bounds__(256, 4) void final_gemm(const float* __restrict__ Wout) {
    __shared__ __align__(16) float As[32][68];
    __shared__ __align__(16) float Bs[32][68];
    int n0 = blockIdx.x * 64, c0 = blockIdx.y * 64, sp = blockIdx.z;
    int tid = threadIdx.x, tx = tid % 16, ty = tid / 16;
    int k0 = sp * 17, k1 = min(66, k0 + 17);
    float acc[4][4] = {};
    for (int kt = k0; kt < k1; kt++) {
        int kb = kt * 32;
        for (int i = tid; i < 2048; i += 256)
            As[i % 32][i / 32] = g_feats[(size_t)(n0 + i/32)*FEAT + kb + (i % 32)];
        for (int i = tid; i < 2048; i += 256)
            Bs[i / 64][i % 64] = Wout[(size_t)(kb + i/64)*CSd + c0 + (i % 64)];
        __syncthreads();
        #pragma unroll
        for (int kk = 0; kk < 32; kk++) {
            float4 a = *(const float4*)&As[kk][ty * 4];
            float4 b = *(const float4*)&Bs[kk][tx * 4];
            FMA16(acc, a, b);
        }
        __syncthreads();
    }
    #pragma unroll
    for (int i = 0; i < 4; i++)
        #pragma unroll
        for (int j = 0; j < 4; j++)
            g_part[(size_t)sp*NN*CSd + (n0 + ty*4 + i)*CSd + c0 + tx*4 + j] = acc[i][j];
}

__global__ void finalize_kernel(const float* __restrict__ bout, float* __restrict__ out) {
    int idx = blockIdx.x * blockDim.x + threadIdx.x;
    if (idx < NN * CSd) {
        int c = idx % CSd;
        out[idx] = bout[c] + g_part[idx] + g_part[NN*CSd + idx]
                 + g_part[2*NN*CSd + idx] + g_part[3*NN*CSd + idx];
    }
}

extern "C" void kernel_launch(void* const* d_in, const int* in_sizes, int n_in,
                              void* d_out, int out_size) {
    const float* s       = (const float*)d_in[0];
    const float* z       = (const float*)d_in[1];
    const float* trans   = (const float*)d_in[2];
    const float* rot     = (const float*)d_in[3];
    const float* Wq  = (const float*)d_in[5];  const float* bq  = (const float*)d_in[6];
    const float* Wk  = (const float*)d_in[7];  const float* bk  = (const float*)d_in[8];
    const float* Wv  = (const float*)d_in[9];  const float* bv  = (const float*)d_in[10];
    const float* Wqp = (const float*)d_in[11]; const float* bqp = (const float*)d_in[12];
    const float* Wkp = (const float*)d_in[13]; const float* bkp = (const float*)d_in[14];
    const float* Wvp = (const float*)d_in[15]; const float* bvp = (const float*)d_in[16];
    const float* Wb  = (const float*)d_in[17]; const float* bb  = (const float*)d_in[18];
    const float* dist_emb      = (const float*)d_in[19];
    const float* scale_logits  = (const float*)d_in[20];
    const float* head_weights  = (const float*)d_in[21];
    const float* Wout = (const float*)d_in[22];
    const float* bout = (const float*)d_in[23];
    float* out = (float*)d_out;

    mid_kernel<<<1168, 256>>>(s, z, trans, Wb, bb, dist_emb, scale_logits,
                              Wq, bq, Wk, bk, Wv, bv, Wqp, bqp, Wkp, bkp, Wvp, bvp);
    geom_kernel<<<NN, 128>>>(trans, rot, head_weights);
    logits_softmax_kernel<<<dim3(32, 12), 256>>>();
    out_kernel<<<608, 256>>>(z);
    assemble_kernel<<<NN, 288>>>(trans, rot);
    final_gemm<<<dim3(8, 6, 4), 256>>>(Wout);
    finalize_kernel<<<(NN*CSd + 255)/256, 256>>>(bout, out);
}